// round 9
// baseline (speedup 1.0000x reference)
#include <cuda_runtime.h>
#include <cuda_bf16.h>
#include <cstdint>
#include <cstdio>
#include <math.h>
#include <float.h>

#define BB 2
#define SS 2048
#define TT 2048
#define NVOCAB 25426
#define NVPAD 25472
#define DD 256
#define HH 8
#define DHH 32
#define NDFF 2048
#define NROWS (BB*TT)
#define T0LEN (TT-1)

// ---------------- scratch ----------------------------------------------------
static __device__ float g_x0 [NROWS*DD];
static __device__ float g_pr [NROWS*DD];
static __device__ float g_x1 [NROWS*DD];
static __device__ float g_x2 [NROWS*DD];
static __device__ float g_x3 [NROWS*DD];
static __device__ int   g_tgt[NROWS];
static __device__ int   g_is64;
// bf16 hi/lo buffers
static __device__ unsigned short g_xh [NROWS*DD],   g_xl [NROWS*DD];
static __device__ unsigned short g_eh [NROWS*DD],   g_el [NROWS*DD];
static __device__ unsigned short g_qkvh[NROWS*3*DD], g_qkvl[NROWS*3*DD];
static __device__ unsigned short g_ath[NROWS*DD],   g_atl[NROWS*DD];
static __device__ unsigned short g_ahi[NROWS*NDFF], g_alo[NROWS*NDFF];
static __device__ unsigned short g_bhi[DD*NVPAD],   g_blo[DD*NVPAD];

// ---------------- helpers ----------------------------------------------------
__device__ __forceinline__ unsigned short bf16_bits(float v) {
    return (unsigned short)__bfloat16_as_ushort(__float2bfloat16(v));
}
__device__ __forceinline__ float bf16_val(unsigned short u) {
    return __bfloat162float(__ushort_as_bfloat16(u));
}
__device__ __forceinline__ unsigned int pack_bf16x2(float lo, float hi) {
    unsigned int r;
    asm("cvt.rn.bf16x2.f32 %0, %1, %2;" : "=r"(r) : "f"(hi), "f"(lo));
    return r;
}
__device__ __forceinline__ float fexp2(float t) {
    t = fmaxf(t, -126.0f);
    float z  = t + 12582912.0f;
    float fi = z - 12582912.0f;
    float f  = t - fi;
    int   ii = __float_as_int(z) - 0x4B400000;
    float p = 1.54035304e-4f;
    p = fmaf(p, f, 1.33335581e-3f);
    p = fmaf(p, f, 9.61812910e-3f);
    p = fmaf(p, f, 5.55041087e-2f);
    p = fmaf(p, f, 2.40226507e-1f);
    p = fmaf(p, f, 6.93147181e-1f);
    p = fmaf(p, f, 1.0f);
    return __int_as_float(__float_as_int(p) + (ii << 23));
}
#define L2E 1.4426950408889634f

// ---------------- prep kernels -----------------------------------------------
__global__ void detect_kernel(const int* __restrict__ raw) {
    __shared__ int any_odd_nonzero;
    if (threadIdx.x == 0) any_odd_nonzero = 0;
    __syncthreads();
    int local = 0;
    for (int i = threadIdx.x; i < BB * T0LEN; i += blockDim.x)
        if ((i & 1) && raw[i] != 0) local = 1;
    if (local) atomicOr(&any_odd_nonzero, 1);
    __syncthreads();
    if (threadIdx.x == 0) g_is64 = any_odd_nonzero ? 0 : 1;
}

__global__ void prep_tgt_kernel(const void* __restrict__ tgt_raw,
                                float* __restrict__ tgt_out) {
    int idx = blockIdx.x * blockDim.x + threadIdx.x;
    if (idx >= NROWS) return;
    int b = idx / TT, t = idx % TT;
    int id;
    if (t == 0) id = NVOCAB;
    else {
        size_t src = (size_t)b * T0LEN + (t - 1);
        if (g_is64) id = (int)((const long long*)tgt_raw)[src];
        else        id = ((const int*)tgt_raw)[src];
    }
    if (id < 0) id = 0;
    if (id > NVOCAB) id = NVOCAB;
    g_tgt[idx] = id;
    if (tgt_out) tgt_out[idx] = (t == 0) ? 0.0f : (float)id;
}

__global__ void embed_kernel(const float* __restrict__ emb,
                             const float* __restrict__ pe) {
    int idx = blockIdx.x * blockDim.x + threadIdx.x;
    if (idx >= NROWS * DD) return;
    int row = idx >> 8, d = idx & 255, t = row & (TT - 1);
    int id = g_tgt[row];
    float v = 2.0f * emb[(size_t)id * DD + d] + pe[(size_t)t * DD + d];
    g_x0[idx] = v;
    unsigned short h = bf16_bits(v);
    g_xh[idx] = h;
    g_xl[idx] = bf16_bits(v - bf16_val(h));
}

__global__ void encmask_kernel(const float* __restrict__ src,
                               const int* __restrict__ mask) {
    int idx = blockIdx.x * blockDim.x + threadIdx.x;
    if (idx >= NROWS * DD) return;
    float v = mask[idx >> 8] ? src[idx] : 0.0f;
    unsigned short h = bf16_bits(v);
    g_eh[idx] = h;
    g_el[idx] = bf16_bits(v - bf16_val(h));
}

__global__ void conv_w4(const float* __restrict__ x,
                        unsigned short* __restrict__ hi,
                        unsigned short* __restrict__ lo,
                        int K, int N, int ldb, int col0) {
    int i = (blockIdx.x * blockDim.x + threadIdx.x) * 4;
    if (i >= K * N) return;
    int r = i / N, c = i % N;
    float4 v = *reinterpret_cast<const float4*>(x + (size_t)r * N + c);
    ushort4 h, l;
    h.x = bf16_bits(v.x); l.x = bf16_bits(v.x - bf16_val(h.x));
    h.y = bf16_bits(v.y); l.y = bf16_bits(v.y - bf16_val(h.y));
    h.z = bf16_bits(v.z); l.z = bf16_bits(v.z - bf16_val(h.z));
    h.w = bf16_bits(v.w); l.w = bf16_bits(v.w - bf16_val(h.w));
    size_t dst = (size_t)r * ldb + col0 + c;
    *reinterpret_cast<ushort4*>(hi + dst) = h;
    *reinterpret_cast<ushort4*>(lo + dst) = l;
}

__global__ void conv_split_pad4(const float* __restrict__ x,
                                unsigned short* __restrict__ hi,
                                unsigned short* __restrict__ lo,
                                int K, int N, int ldb) {
    int i = (blockIdx.x * blockDim.x + threadIdx.x) * 4;
    if (i >= K * ldb) return;
    int r = i / ldb, c = i % ldb;
    float vv[4];
    #pragma unroll
    for (int j = 0; j < 4; j++) {
        int cc = c + j;
        vv[j] = (cc < N) ? x[(size_t)r * N + cc] : 0.0f;
    }
    ushort4 h, l;
    h.x = bf16_bits(vv[0]); l.x = bf16_bits(vv[0] - bf16_val(h.x));
    h.y = bf16_bits(vv[1]); l.y = bf16_bits(vv[1] - bf16_val(h.y));
    h.z = bf16_bits(vv[2]); l.z = bf16_bits(vv[2] - bf16_val(h.z));
    h.w = bf16_bits(vv[3]); l.w = bf16_bits(vv[3] - bf16_val(h.w));
    *reinterpret_cast<ushort4*>(hi + i) = h;
    *reinterpret_cast<ushort4*>(lo + i) = l;
}

// ---------------- MMA primitives ---------------------------------------------
#define MMA_BF16(ac, a, b0, b1)                                              \
    asm volatile("mma.sync.aligned.m16n8k16.row.col.f32.bf16.bf16.f32 "      \
                 "{%0,%1,%2,%3},{%4,%5,%6,%7},{%8,%9},{%0,%1,%2,%3};"        \
                 : "+f"(ac[0]), "+f"(ac[1]), "+f"(ac[2]), "+f"(ac[3])        \
                 : "r"(a[0]), "r"(a[1]), "r"(a[2]), "r"(a[3]),               \
                   "r"(b0), "r"(b1))

__device__ __forceinline__ void ldsm_x4(unsigned int* r, const unsigned short* p) {
    unsigned int sa = (unsigned int)__cvta_generic_to_shared(p);
    asm volatile("ldmatrix.sync.aligned.m8n8.x4.shared.b16 {%0,%1,%2,%3},[%4];"
                 : "=r"(r[0]), "=r"(r[1]), "=r"(r[2]), "=r"(r[3]) : "r"(sa));
}
__device__ __forceinline__ void ldsm_x4t(unsigned int* r, const unsigned short* p) {
    unsigned int sa = (unsigned int)__cvta_generic_to_shared(p);
    asm volatile("ldmatrix.sync.aligned.m8n8.x4.trans.shared.b16 {%0,%1,%2,%3},[%4];"
                 : "=r"(r[0]), "=r"(r[1]), "=r"(r[2]), "=r"(r[3]) : "r"(sa));
}
__device__ __forceinline__ void cp16(unsigned short* sdst, const unsigned short* gsrc) {
    unsigned int d = (unsigned int)__cvta_generic_to_shared(sdst);
    asm volatile("cp.async.cg.shared.global [%0], [%1], 16;" :: "r"(d), "l"(gsrc));
}
#define CP_COMMIT() asm volatile("cp.async.commit_group;" ::: "memory")
#define CP_WAIT0()  asm volatile("cp.async.wait_group 0;" ::: "memory")
#define CP_WAIT1()  asm volatile("cp.async.wait_group 1;" ::: "memory")

// ---------------- tensor-core GEMM: BM128 x BN128 x BK32, 8 warps (2x4) ------
#define LDA_S 40                      // 32 + 8 pad
#define LDB_S 136                     // 128 + 8 pad
#define A_H_OFF 0
#define A_L_OFF (128*LDA_S)           // 5120
#define B_H_OFF (2*128*LDA_S)         // 10240
#define B_L_OFF (2*128*LDA_S + 32*LDB_S)   // 14592
#define STAGE_SZ (2*128*LDA_S + 2*32*LDB_S) // 18944 ushorts
#define SMEM_BYTES (2 * STAGE_SZ * 2)       // 75776 B

// OUTM 0: fp32 C (stride ldc). OUTM 1: bf16 hi/lo Ch/Cl (stride ldc).
template<int ACT, int OUTM>
__global__ __launch_bounds__(256, 1)
void mma_gemm(const unsigned short* __restrict__ Ahi,
              const unsigned short* __restrict__ Alo,
              const unsigned short* __restrict__ Bhi,
              const unsigned short* __restrict__ Blo,
              const float* __restrict__ bias, float* __restrict__ C,
              unsigned short* __restrict__ Ch, unsigned short* __restrict__ Cl,
              int M, int N, int K, int ldb, int ldc) {
    extern __shared__ __align__(16) unsigned short smem_u[];

    const int tid = threadIdx.x, lane = tid & 31, warp = tid >> 5;
    const int wm = warp >> 2, wn = warp & 3;           // 2x4 warp grid
    const int m0 = blockIdx.y * 128, n0 = blockIdx.x * 128;
    const int ar = tid >> 1, ac = (tid & 1) * 16;      // A: 128 rows x 32
    const int br = tid >> 3, bc = (tid & 7) * 16;      // B: 32 rows x 128

    float acc[4][4][4] = {};

    auto issue_tile = [&](int k0, int st) {
        unsigned short* base = smem_u + st * STAGE_SZ;
        const unsigned short* gAh = Ahi + (size_t)(m0 + ar) * K + k0 + ac;
        const unsigned short* gAl = Alo + (size_t)(m0 + ar) * K + k0 + ac;
        cp16(base + A_H_OFF + ar * LDA_S + ac,     gAh);
        cp16(base + A_H_OFF + ar * LDA_S + ac + 8, gAh + 8);
        cp16(base + A_L_OFF + ar * LDA_S + ac,     gAl);
        cp16(base + A_L_OFF + ar * LDA_S + ac + 8, gAl + 8);
        const size_t gb = (size_t)(k0 + br) * ldb + n0 + bc;
        cp16(base + B_H_OFF + br * LDB_S + bc,     Bhi + gb);
        cp16(base + B_H_OFF + br * LDB_S + bc + 8, Bhi + gb + 8);
        cp16(base + B_L_OFF + br * LDB_S + bc,     Blo + gb);
        cp16(base + B_L_OFF + br * LDB_S + bc + 8, Blo + gb + 8);
    };

    issue_tile(0, 0);
    CP_COMMIT();

    int buf = 0;
    for (int k0 = 0; k0 < K; k0 += 32) {
        if (k0 + 32 < K) { issue_tile(k0 + 32, buf ^ 1); CP_COMMIT(); CP_WAIT1(); }
        else             { CP_WAIT0(); }
        __syncthreads();

        const unsigned short* sAh = smem_u + buf * STAGE_SZ + A_H_OFF;
        const unsigned short* sAl = smem_u + buf * STAGE_SZ + A_L_OFF;
        const unsigned short* sBh = smem_u + buf * STAGE_SZ + B_H_OFF;
        const unsigned short* sBl = smem_u + buf * STAGE_SZ + B_L_OFF;

        #pragma unroll
        for (int ks = 0; ks < 32; ks += 16) {
            unsigned int ah[4][4], al[4][4];
            #pragma unroll
            for (int mi = 0; mi < 4; mi++) {
                const int off = (wm * 64 + mi * 16 + (lane & 15)) * LDA_S
                                + ks + (lane >> 4) * 8;
                ldsm_x4(ah[mi], &sAh[off]);
                ldsm_x4(al[mi], &sAl[off]);
            }
            unsigned int bh[2][4], bl[2][4];
            #pragma unroll
            for (int p = 0; p < 2; p++) {
                const int off = (ks + (lane & 15)) * LDB_S
                                + wn * 32 + p * 16 + (lane >> 4) * 8;
                ldsm_x4t(bh[p], &sBh[off]);
                ldsm_x4t(bl[p], &sBl[off]);
            }
            #pragma unroll
            for (int mi = 0; mi < 4; mi++) {
                #pragma unroll
                for (int ni = 0; ni < 4; ni++) {
                    unsigned int bh0 = bh[ni >> 1][(ni & 1) * 2];
                    unsigned int bh1 = bh[ni >> 1][(ni & 1) * 2 + 1];
                    unsigned int bl0 = bl[ni >> 1][(ni & 1) * 2];
                    unsigned int bl1 = bl[ni >> 1][(ni & 1) * 2 + 1];
                    MMA_BF16(acc[mi][ni], ah[mi], bh0, bh1);
                    MMA_BF16(acc[mi][ni], ah[mi], bl0, bl1);
                    MMA_BF16(acc[mi][ni], al[mi], bh0, bh1);
                }
            }
        }
        __syncthreads();
        buf ^= 1;
    }

    const int grp = lane >> 2, t4 = lane & 3;
    #pragma unroll
    for (int mi = 0; mi < 4; mi++) {
        #pragma unroll
        for (int ni = 0; ni < 4; ni++) {
            int row = m0 + wm * 64 + mi * 16 + grp;
            int col = n0 + wn * 32 + ni * 8 + t4 * 2;
            #pragma unroll
            for (int hv = 0; hv < 2; hv++) {
                int r = row + hv * 8;
                #pragma unroll
                for (int cc = 0; cc < 2; cc++) {
                    int n = col + cc;
                    if (n >= N) continue;
                    float v = acc[mi][ni][hv * 2 + cc] + (bias ? bias[n] : 0.0f);
                    if (ACT == 1) v = 0.5f * v * (1.0f + erff(v * 0.70710678118654752f));
                    if (OUTM == 0) {
                        C[(size_t)r * ldc + n] = v;
                    } else {
                        unsigned short h = bf16_bits(v);
                        Ch[(size_t)r * ldc + n] = h;
                        Cl[(size_t)r * ldc + n] = bf16_bits(v - bf16_val(h));
                    }
                }
            }
        }
    }
}

// ---------------- tensor-core flash attention (unchanged) --------------------
#define LDK 40
#define ATT_SCALE 0.17677669529663687f
#define QKV_LD (3*DD)

template<int MODE>
__global__ __launch_bounds__(128)
void attn_mma(const unsigned short* __restrict__ Qh, const unsigned short* __restrict__ Ql,
              const unsigned short* __restrict__ Kh, const unsigned short* __restrict__ Kl,
              const unsigned short* __restrict__ Vh, const unsigned short* __restrict__ Vl,
              unsigned short* __restrict__ Oh, unsigned short* __restrict__ Ol,
              const int* __restrict__ aux) {
    const int b = blockIdx.z, h = blockIdx.y, blk = blockIdx.x;
    const int tid = threadIdx.x, lane = tid & 31, w = tid >> 5;
    const int grp = lane >> 2, t4 = lane & 3;
    const size_t rowbase = (size_t)b * TT * QKV_LD + h * DHH;
    const size_t obase   = (size_t)b * TT * DD + h * DHH;

    __shared__ __align__(16) unsigned short sQh[64*LDK], sQl[64*LDK];
    __shared__ __align__(16) unsigned short sKh[64*LDK], sKl[64*LDK];
    __shared__ __align__(16) unsigned short sVh[64*LDK], sVl[64*LDK];
    __shared__ int sMask[64];

    {
        int r = tid >> 1, cs = (tid & 1) * 16;
        size_t g = rowbase + (size_t)(blk * 64 + r) * QKV_LD + cs;
        *(uint4*)&sQh[r*LDK+cs]   = *(const uint4*)(Qh + g);
        *(uint4*)&sQh[r*LDK+cs+8] = *(const uint4*)(Qh + g + 8);
        *(uint4*)&sQl[r*LDK+cs]   = *(const uint4*)(Ql + g);
        *(uint4*)&sQl[r*LDK+cs+8] = *(const uint4*)(Ql + g + 8);
    }

    const int qi0 = blk * 64 + w * 16 + grp;
    const int qi1 = qi0 + 8;
    bool qv0 = true, qv1 = true;
    int pred = 0;
    if (MODE == 0) {
        qv0 = (g_tgt[b * TT + qi0] != 0);
        qv1 = (g_tgt[b * TT + qi1] != 0);
        pred = (tid < 64) && (g_tgt[b * TT + blk * 64 + tid] == 0);
    }
    int ext = __syncthreads_or(pred);

    unsigned int qfh[2][4], qfl[2][4];
    #pragma unroll
    for (int c = 0; c < 2; c++) {
        const int off = (w * 16 + (lane & 15)) * LDK + c * 16 + (lane >> 4) * 8;
        ldsm_x4(qfh[c], &sQh[off]);
        ldsm_x4(qfl[c], &sQl[off]);
    }

    const int nT = (MODE == 0) ? (ext ? TT / 64 : (blk + 1)) : SS / 64;

    float M0 = -FLT_MAX, M1 = -FLT_MAX, L0 = 0.0f, L1 = 0.0f;
    float O[4][4] = {};

    for (int tile = 0; tile < nT; tile++) {
        const int j0 = tile * 64;
        __syncthreads();
        {
            int r = tid >> 1, cs = (tid & 1) * 16;
            size_t g = rowbase + (size_t)(j0 + r) * QKV_LD + cs;
            *(uint4*)&sKh[r*LDK+cs]   = *(const uint4*)(Kh + g);
            *(uint4*)&sKh[r*LDK+cs+8] = *(const uint4*)(Kh + g + 8);
            *(uint4*)&sKl[r*LDK+cs]   = *(const uint4*)(Kl + g);
            *(uint4*)&sKl[r*LDK+cs+8] = *(const uint4*)(Kl + g + 8);
            *(uint4*)&sVh[r*LDK+cs]   = *(const uint4*)(Vh + g);
            *(uint4*)&sVh[r*LDK+cs+8] = *(const uint4*)(Vh + g + 8);
            *(uint4*)&sVl[r*LDK+cs]   = *(const uint4*)(Vl + g);
            *(uint4*)&sVl[r*LDK+cs+8] = *(const uint4*)(Vl + g + 8);
            if (MODE == 1 && tid < 64) sMask[tid] = aux[b * SS + j0 + tid];
        }
        __syncthreads();

        float sc[8][4] = {};
        #pragma unroll
        for (int c = 0; c < 2; c++) {
            #pragma unroll
            for (int g4 = 0; g4 < 4; g4++) {
                unsigned int kbh[4], kbl[4];
                const int off = (g4 * 16 + (lane & 15)) * LDK + c * 16 + (lane >> 4) * 8;
                ldsm_x4(kbh, &sKh[off]);
                ldsm_x4(kbl, &sKl[off]);
                MMA_BF16(sc[2*g4],   qfh[c], kbh[0], kbh[2]);
                MMA_BF16(sc[2*g4],   qfh[c], kbl[0], kbl[2]);
                MMA_BF16(sc[2*g4],   qfl[c], kbh[0], kbh[2]);
                MMA_BF16(sc[2*g4+1], qfh[c], kbh[1], kbh[3]);
                MMA_BF16(sc[2*g4+1], qfh[c], kbl[1], kbl[3]);
                MMA_BF16(sc[2*g4+1], qfl[c], kbh[1], kbh[3]);
            }
        }

        float ml0 = -FLT_MAX, ml1 = -FLT_MAX;
        #pragma unroll
        for (int f = 0; f < 8; f++) {
            const int jc = j0 + f * 8 + t4 * 2;
            bool v00, v01, v10, v11;
            if (MODE == 0) {
                v00 = qv0 && (jc     <= qi0);
                v01 = qv0 && (jc + 1 <= qi0);
                v10 = qv1 && (jc     <= qi1);
                v11 = qv1 && (jc + 1 <= qi1);
            } else {
                bool k0m = sMask[f * 8 + t4 * 2]     != 0;
                bool k1m = sMask[f * 8 + t4 * 2 + 1] != 0;
                v00 = k0m; v01 = k1m; v10 = k0m; v11 = k1m;
            }
            sc[f][0] = v00 ? sc[f][0] * ATT_SCALE : -FLT_MAX;
            sc[f][1] = v01 ? sc[f][1] * ATT_SCALE : -FLT_MAX;
            sc[f][2] = v10 ? sc[f][2] * ATT_SCALE : -FLT_MAX;
            sc[f][3] = v11 ? sc[f][3] * ATT_SCALE : -FLT_MAX;
            ml0 = fmaxf(ml0, fmaxf(sc[f][0], sc[f][1]));
            ml1 = fmaxf(ml1, fmaxf(sc[f][2], sc[f][3]));
        }
        ml0 = fmaxf(ml0, __shfl_xor_sync(0xffffffffu, ml0, 1));
        ml0 = fmaxf(ml0, __shfl_xor_sync(0xffffffffu, ml0, 2));
        ml1 = fmaxf(ml1, __shfl_xor_sync(0xffffffffu, ml1, 1));
        ml1 = fmaxf(ml1, __shfl_xor_sync(0xffffffffu, ml1, 2));

        const float mn0 = fmaxf(M0, ml0), mn1 = fmaxf(M1, ml1);
        const float corr0 = fexp2((M0 - mn0) * L2E);
        const float corr1 = fexp2((M1 - mn1) * L2E);
        L0 *= corr0; L1 *= corr1;
        #pragma unroll
        for (int ni = 0; ni < 4; ni++) {
            O[ni][0] *= corr0; O[ni][1] *= corr0;
            O[ni][2] *= corr1; O[ni][3] *= corr1;
        }

        float ls0 = 0.0f, ls1 = 0.0f;
        unsigned int aH0[8], aH1[8], aL0[8], aL1[8];
        #pragma unroll
        for (int f = 0; f < 8; f++) {
            float p0 = fexp2((sc[f][0] - mn0) * L2E);
            float p1 = fexp2((sc[f][1] - mn0) * L2E);
            float p2 = fexp2((sc[f][2] - mn1) * L2E);
            float p3 = fexp2((sc[f][3] - mn1) * L2E);
            ls0 += p0 + p1; ls1 += p2 + p3;
            unsigned short h0 = bf16_bits(p0), h1 = bf16_bits(p1);
            unsigned short h2 = bf16_bits(p2), h3 = bf16_bits(p3);
            aH0[f] = (unsigned int)h0 | ((unsigned int)h1 << 16);
            aH1[f] = (unsigned int)h2 | ((unsigned int)h3 << 16);
            aL0[f] = pack_bf16x2(p0 - bf16_val(h0), p1 - bf16_val(h1));
            aL1[f] = pack_bf16x2(p2 - bf16_val(h2), p3 - bf16_val(h3));
        }
        ls0 += __shfl_xor_sync(0xffffffffu, ls0, 1);
        ls0 += __shfl_xor_sync(0xffffffffu, ls0, 2);
        ls1 += __shfl_xor_sync(0xffffffffu, ls1, 1);
        ls1 += __shfl_xor_sync(0xffffffffu, ls1, 2);
        L0 += ls0; L1 += ls1;
        M0 = mn0; M1 = mn1;

        #pragma unroll
        for (int kc = 0; kc < 4; kc++) {
            unsigned int pah[4] = { aH0[2*kc], aH1[2*kc], aH0[2*kc+1], aH1[2*kc+1] };
            unsigned int pal[4] = { aL0[2*kc], aL1[2*kc], aL0[2*kc+1], aL1[2*kc+1] };
            #pragma unroll
            for (int ph = 0; ph < 2; ph++) {
                unsigned int vbh[4], vbl[4];
                const int off = (kc * 16 + (lane & 15)) * LDK + ph * 16 + (lane >> 4) * 8;
                ldsm_x4t(vbh, &sVh[off]);
                ldsm_x4t(vbl, &sVl[off]);
                #pragma unroll
                for (int j = 0; j < 2; j++) {
                    const int ni = ph * 2 + j;
                    MMA_BF16(O[ni], pah, vbh[2*j], vbh[2*j+1]);
                    MMA_BF16(O[ni], pah, vbl[2*j], vbl[2*j+1]);
                    MMA_BF16(O[ni], pal, vbh[2*j], vbh[2*j+1]);
                }
            }
        }
    }

    const float inv0 = 1.0f / L0, inv1 = 1.0f / L1;
    const size_t o0 = obase + (size_t)qi0 * DD;
    const size_t o1 = obase + (size_t)qi1 * DD;
    #pragma unroll
    for (int ni = 0; ni < 4; ni++) {
        const int n = ni * 8 + t4 * 2;
        float v00 = O[ni][0] * inv0, v01 = O[ni][1] * inv0;
        float v10 = O[ni][2] * inv1, v11 = O[ni][3] * inv1;
        unsigned short h;
        h = bf16_bits(v00); Oh[o0 + n]     = h; Ol[o0 + n]     = bf16_bits(v00 - bf16_val(h));
        h = bf16_bits(v01); Oh[o0 + n + 1] = h; Ol[o0 + n + 1] = bf16_bits(v01 - bf16_val(h));
        h = bf16_bits(v10); Oh[o1 + n]     = h; Ol[o1 + n]     = bf16_bits(v10 - bf16_val(h));
        h = bf16_bits(v11); Oh[o1 + n + 1] = h; Ol[o1 + n + 1] = bf16_bits(v11 - bf16_val(h));
    }
}

// ---------------- residual + layernorm (+ hi/lo split) -----------------------
__global__ __launch_bounds__(128)
void ln_kernel(const float* __restrict__ x, const float* __restrict__ h,
               const float* __restrict__ g, const float* __restrict__ bvec,
               float* __restrict__ y,
               unsigned short* __restrict__ yh, unsigned short* __restrict__ yl) {
    int row = blockIdx.x * 4 + (threadIdx.x >> 5);
    int lane = threadIdx.x & 31;
    const float* xr = x + (size_t)row * DD;
    const float* hr = h + (size_t)row * DD;
    float vals[8];
    float s = 0.0f;
    #pragma unroll
    for (int u = 0; u < 8; u++) {
        int c = lane + u * 32;
        vals[u] = xr[c] + hr[c];
        s += vals[u];
    }
    #pragma unroll
    for (int off = 16; off > 0; off >>= 1) s += __shfl_xor_sync(0xffffffffu, s, off);
    float mean = s * (1.0f / DD);
    float vs = 0.0f;
    #pragma unroll
    for (int u = 0; u < 8; u++) { float d = vals[u] - mean; vs += d * d; }
    #pragma unroll
    for (int off = 16; off > 0; off >>= 1) vs += __shfl_xor_sync(0xffffffffu, vs, off);
    float inv = rsqrtf(vs * (1.0f / DD) + 1e-5f);
    float* yr = y + (size_t)row * DD;
    #pragma unroll
    for (int u = 0; u < 8; u++) {
        int c = lane + u * 32;
        float v = (vals[u] - mean) * inv * g[c] + bvec[c];
        yr[c] = v;
        unsigned short hb = bf16_bits(v);
        yh[(size_t)row * DD + c] = hb;
        yl[(size_t)row * DD + c] = bf16_bits(v - bf16_val(hb));
    }
}

// ---------------- launch -----------------------------------------------------
extern "C" void kernel_launch(void* const* d_in, const int* in_sizes, int n_in,
                              void* d_out, int out_size) {
    const float* src_embedded = (const float*)d_in[0];
    const int*   src_mask     = (const int*)d_in[1];
    const void*  tgt_raw      = d_in[2];
    const float* emb   = (const float*)d_in[3];
    const float* pe    = (const float*)d_in[4];
    const float* sa_wq = (const float*)d_in[5];
    const float* sa_wk = (const float*)d_in[6];
    const float* sa_wv = (const float*)d_in[7];
    const float* sa_wo = (const float*)d_in[8];
    const float* sa_bo = (const float*)d_in[9];
    const float* ca_wq = (const float*)d_in[10];
    const float* ca_wk = (const float*)d_in[11];
    const float* ca_wv = (const float*)d_in[12];
    const float* ca_wo = (const float*)d_in[13];
    const float* ca_bo = (const float*)d_in[14];
    const float* ln1_g = (const float*)d_in[15];
    const float* ln1_b = (const float*)d_in[16];
    const float* ln2_g = (const float*)d_in[17];
    const float* ln2_b = (const float*)d_in[18];
    const float* ln3_g = (const float*)d_in[19];
    const float* ln3_b = (const float*)d_in[20];
    const float* fc1_w = (const float*)d_in[21];
    const float* fc1_b = (const float*)d_in[22];
    const float* fc2_w = (const float*)d_in[23];
    const float* fc2_b = (const float*)d_in[24];
    const float* out_w = (const float*)d_in[25];
    const float* out_b = (const float*)d_in[26];

    float *x0, *pr, *x1, *x2, *x3;
    unsigned short *xh, *xl, *eh, *el, *qkvh, *qkvl, *ath, *atl, *ahi, *alo, *bhi, *blo;
    cudaGetSymbolAddress((void**)&x0,   g_x0);
    cudaGetSymbolAddress((void**)&pr,   g_pr);
    cudaGetSymbolAddress((void**)&x1,   g_x1);
    cudaGetSymbolAddress((void**)&x2,   g_x2);
    cudaGetSymbolAddress((void**)&x3,   g_x3);
    cudaGetSymbolAddress((void**)&xh,   g_xh);
    cudaGetSymbolAddress((void**)&xl,   g_xl);
    cudaGetSymbolAddress((void**)&eh,   g_eh);
    cudaGetSymbolAddress((void**)&el,   g_el);
    cudaGetSymbolAddress((void**)&qkvh, g_qkvh);
    cudaGetSymbolAddress((void**)&qkvl, g_qkvl);
    cudaGetSymbolAddress((void**)&ath,  g_ath);
    cudaGetSymbolAddress((void**)&atl,  g_atl);
    cudaGetSymbolAddress((void**)&ahi,  g_ahi);
    cudaGetSymbolAddress((void**)&alo,  g_alo);
    cudaGetSymbolAddress((void**)&bhi,  g_bhi);
    cudaGetSymbolAddress((void**)&blo,  g_blo);

    cudaFuncSetAttribute(mma_gemm<0,0>, cudaFuncAttributeMaxDynamicSharedMemorySize, SMEM_BYTES);
    cudaFuncSetAttribute(mma_gemm<0,1>, cudaFuncAttributeMaxDynamicSharedMemorySize, SMEM_BYTES);
    cudaFuncSetAttribute(mma_gemm<1,1>, cudaFuncAttributeMaxDynamicSharedMemorySize, SMEM_BYTES);

    float* outp   = (float*)d_out;
    float* logits = outp;
    float* tgt_out = nullptr;
    long long need = (long long)NROWS * NVOCAB;
    if ((long long)out_size >= need + NROWS) tgt_out = outp + need;

    detect_kernel<<<1, 256>>>((const int*)tgt_raw);
    prep_tgt_kernel<<<(NROWS + 127) / 128, 128>>>(tgt_raw, tgt_out);
    embed_kernel<<<(NROWS * DD) / 256, 256>>>(emb, pe);

    dim3 gD(DD / 128, NROWS / 128);                // (2, 32)
    dim3 gQKV((3 * DD) / 128, NROWS / 128);        // (6, 32)
    dim3 gKV((2 * DD) / 128, NROWS / 128);         // (4, 32)
    dim3 gF(NDFF / 128, NROWS / 128);              // (16, 32)
    dim3 gV(NVPAD / 128, NROWS / 128);             // (199, 32)
    dim3 gAttn(TT / 64, HH, BB);
    const int WB = 256;

    // ---- self-attention block ----
    conv_w4<<<(DD*DD)/(4*WB), WB>>>(sa_wq, bhi, blo, DD, DD, 3*DD, 0);
    conv_w4<<<(DD*DD)/(4*WB), WB>>>(sa_wk, bhi, blo, DD, DD, 3*DD, DD);
    conv_w4<<<(DD*DD)/(4*WB), WB>>>(sa_wv, bhi, blo, DD, DD, 3*DD, 2*DD);
    mma_gemm<0,1><<<gQKV, 256, SMEM_BYTES>>>(xh, xl, bhi, blo, nullptr, nullptr,
                                             qkvh, qkvl, NROWS, 3*DD, DD, 3*DD, 3*DD);
    attn_mma<0><<<gAttn, 128>>>(qkvh, qkvl, qkvh + DD, qkvl + DD,
                                qkvh + 2*DD, qkvl + 2*DD, ath, atl, nullptr);
    conv_w4<<<(DD*DD)/(4*WB), WB>>>(sa_wo, bhi, blo, DD, DD, DD, 0);
    mma_gemm<0,0><<<gD, 256, SMEM_BYTES>>>(ath, atl, bhi, blo, sa_bo, pr,
                                           nullptr, nullptr, NROWS, DD, DD, DD, DD);
    ln_kernel<<<NROWS / 4, 128>>>(x0, pr, ln1_g, ln1_b, x1, xh, xl);

    // ---- cross-attention block ----
    encmask_kernel<<<(NROWS * DD) / 256, 256>>>(src_embedded, src_mask);
    conv_w4<<<(DD*DD)/(4*WB), WB>>>(ca_wq, bhi, blo, DD, DD, DD, 0);
    mma_gemm<0,1><<<gD, 256, SMEM_BYTES>>>(xh, xl, bhi, blo, nullptr, nullptr,
                                           qkvh, qkvl, NROWS, DD, DD, DD, 3*DD);
    conv_w4<<<(DD*DD)/(4*WB), WB>>>(ca_wk, bhi, blo, DD, DD, 2*DD, 0);
    conv_w4<<<(DD*DD)/(4*WB), WB>>>(ca_wv, bhi, blo, DD, DD, 2*DD, DD);
    mma_gemm<0,1><<<gKV, 256, SMEM_BYTES>>>(eh, el, bhi, blo, nullptr, nullptr,
                                            qkvh + DD, qkvl + DD, NROWS, 2*DD, DD, 2*DD, 3*DD);
    attn_mma<1><<<gAttn, 128>>>(qkvh, qkvl, qkvh + DD, qkvl + DD,
                                qkvh + 2*DD, qkvl + 2*DD, ath, atl, src_mask);
    conv_w4<<<(DD*DD)/(4*WB), WB>>>(ca_wo, bhi, blo, DD, DD, DD, 0);
    mma_gemm<0,0><<<gD, 256, SMEM_BYTES>>>(ath, atl, bhi, blo, ca_bo, pr,
                                           nullptr, nullptr, NROWS, DD, DD, DD, DD);
    ln_kernel<<<NROWS / 4, 128>>>(x1, pr, ln2_g, ln2_b, x2, xh, xl);

    // ---- FFN ----
    conv_w4<<<(DD*NDFF)/(4*WB), WB>>>(fc1_w, bhi, blo, DD, NDFF, NDFF, 0);
    mma_gemm<1,1><<<gF, 256, SMEM_BYTES>>>(xh, xl, bhi, blo, fc1_b, nullptr,
                                           ahi, alo, NROWS, NDFF, DD, NDFF, NDFF);
    conv_w4<<<(NDFF*DD)/(4*WB), WB>>>(fc2_w, bhi, blo, NDFF, DD, DD, 0);
    mma_gemm<0,0><<<gD, 256, SMEM_BYTES>>>(ahi, alo, bhi, blo, fc2_b, pr,
                                           nullptr, nullptr, NROWS, DD, NDFF, DD, DD);
    ln_kernel<<<NROWS / 4, 128>>>(x2, pr, ln3_g, ln3_b, x3, xh, xl);

    // ---- vocab projection ----
    conv_split_pad4<<<(DD*NVPAD)/(4*WB), WB>>>(out_w, bhi, blo, DD, NVOCAB, NVPAD);
    mma_gemm<0,0><<<gV, 256, SMEM_BYTES>>>(xh, xl, bhi, blo, out_b, logits,
                                           nullptr, nullptr, NROWS, NVOCAB, DD, NVPAD, NVOCAB);
}

// round 10
// speedup vs baseline: 1.1019x; 1.1019x over previous
#include <cuda_runtime.h>
#include <cuda_bf16.h>
#include <cstdint>
#include <cstdio>
#include <math.h>
#include <float.h>

#define BB 2
#define SS 2048
#define TT 2048
#define NVOCAB 25426
#define NVPAD 25472
#define DD 256
#define HH 8
#define DHH 32
#define NDFF 2048
#define NROWS (BB*TT)
#define T0LEN (TT-1)

// ---------------- scratch ----------------------------------------------------
static __device__ float g_x0 [NROWS*DD];
static __device__ float g_pr [NROWS*DD];
static __device__ float g_x1 [NROWS*DD];
static __device__ float g_x2 [NROWS*DD];
static __device__ float g_x3 [NROWS*DD];
static __device__ int   g_tgt[NROWS];
// bf16 hi/lo buffers
static __device__ unsigned short g_xh [NROWS*DD],   g_xl [NROWS*DD];
static __device__ unsigned short g_eh [NROWS*DD],   g_el [NROWS*DD];
static __device__ unsigned short g_qkvh[NROWS*3*DD], g_qkvl[NROWS*3*DD];
static __device__ unsigned short g_ath[NROWS*DD],   g_atl[NROWS*DD];
static __device__ unsigned short g_ahi[NROWS*NDFF], g_alo[NROWS*NDFF];
static __device__ unsigned short g_bhi[DD*NVPAD],   g_blo[DD*NVPAD];

// ---------------- helpers ----------------------------------------------------
__device__ __forceinline__ unsigned short bf16_bits(float v) {
    return (unsigned short)__bfloat16_as_ushort(__float2bfloat16(v));
}
__device__ __forceinline__ float bf16_val(unsigned short u) {
    return __bfloat162float(__ushort_as_bfloat16(u));
}
__device__ __forceinline__ unsigned int pack_bf16x2(float lo, float hi) {
    unsigned int r;
    asm("cvt.rn.bf16x2.f32 %0, %1, %2;" : "=r"(r) : "f"(hi), "f"(lo));
    return r;
}
__device__ __forceinline__ float fexp2(float t) {
    t = fmaxf(t, -126.0f);
    float z  = t + 12582912.0f;
    float fi = z - 12582912.0f;
    float f  = t - fi;
    int   ii = __float_as_int(z) - 0x4B400000;
    float p = 1.54035304e-4f;
    p = fmaf(p, f, 1.33335581e-3f);
    p = fmaf(p, f, 9.61812910e-3f);
    p = fmaf(p, f, 5.55041087e-2f);
    p = fmaf(p, f, 2.40226507e-1f);
    p = fmaf(p, f, 6.93147181e-1f);
    p = fmaf(p, f, 1.0f);
    return __int_as_float(__float_as_int(p) + (ii << 23));
}
#define L2E 1.4426950408889634f

// ---------------- prep kernels -----------------------------------------------
// prep_tgt with per-block inline dtype detection (deterministic per input)
__global__ void prep_tgt_kernel(const void* __restrict__ tgt_raw,
                                float* __restrict__ tgt_out) {
    __shared__ int s_odd;
    if (threadIdx.x == 0) s_odd = 0;
    __syncthreads();
    const int* raw = (const int*)tgt_raw;
    int local = 0;
    for (int i = threadIdx.x; i < BB * T0LEN; i += blockDim.x)
        if ((i & 1) && raw[i] != 0) local = 1;
    if (local) atomicOr(&s_odd, 1);
    __syncthreads();
    int is64 = s_odd ? 0 : 1;

    int idx = blockIdx.x * blockDim.x + threadIdx.x;
    if (idx >= NROWS) return;
    int b = idx / TT, t = idx % TT;
    int id;
    if (t == 0) id = NVOCAB;
    else {
        size_t src = (size_t)b * T0LEN + (t - 1);
        if (is64) id = (int)((const long long*)tgt_raw)[src];
        else      id = ((const int*)tgt_raw)[src];
    }
    if (id < 0) id = 0;
    if (id > NVOCAB) id = NVOCAB;
    g_tgt[idx] = id;
    if (tgt_out) tgt_out[idx] = (t == 0) ? 0.0f : (float)id;
}

__global__ void embed_kernel(const float* __restrict__ emb,
                             const float* __restrict__ pe) {
    int idx = blockIdx.x * blockDim.x + threadIdx.x;
    if (idx >= NROWS * DD) return;
    int row = idx >> 8, d = idx & 255, t = row & (TT - 1);
    int id = g_tgt[row];
    float v = 2.0f * emb[(size_t)id * DD + d] + pe[(size_t)t * DD + d];
    g_x0[idx] = v;
    unsigned short h = bf16_bits(v);
    g_xh[idx] = h;
    g_xl[idx] = bf16_bits(v - bf16_val(h));
}

__global__ void encmask_kernel(const float* __restrict__ src,
                               const int* __restrict__ mask) {
    int idx = blockIdx.x * blockDim.x + threadIdx.x;
    if (idx >= NROWS * DD) return;
    float v = mask[idx >> 8] ? src[idx] : 0.0f;
    unsigned short h = bf16_bits(v);
    g_eh[idx] = h;
    g_el[idx] = bf16_bits(v - bf16_val(h));
}

__global__ void conv_w4(const float* __restrict__ x,
                        unsigned short* __restrict__ hi,
                        unsigned short* __restrict__ lo,
                        int K, int N, int ldb, int col0) {
    int i = (blockIdx.x * blockDim.x + threadIdx.x) * 4;
    if (i >= K * N) return;
    int r = i / N, c = i % N;
    float4 v = *reinterpret_cast<const float4*>(x + (size_t)r * N + c);
    ushort4 h, l;
    h.x = bf16_bits(v.x); l.x = bf16_bits(v.x - bf16_val(h.x));
    h.y = bf16_bits(v.y); l.y = bf16_bits(v.y - bf16_val(h.y));
    h.z = bf16_bits(v.z); l.z = bf16_bits(v.z - bf16_val(h.z));
    h.w = bf16_bits(v.w); l.w = bf16_bits(v.w - bf16_val(h.w));
    size_t dst = (size_t)r * ldb + col0 + c;
    *reinterpret_cast<ushort4*>(hi + dst) = h;
    *reinterpret_cast<ushort4*>(lo + dst) = l;
}

__global__ void conv_split_pad4(const float* __restrict__ x,
                                unsigned short* __restrict__ hi,
                                unsigned short* __restrict__ lo,
                                int K, int N, int ldb) {
    int i = (blockIdx.x * blockDim.x + threadIdx.x) * 4;
    if (i >= K * ldb) return;
    int r = i / ldb, c = i % ldb;
    float vv[4];
    #pragma unroll
    for (int j = 0; j < 4; j++) {
        int cc = c + j;
        vv[j] = (cc < N) ? x[(size_t)r * N + cc] : 0.0f;
    }
    ushort4 h, l;
    h.x = bf16_bits(vv[0]); l.x = bf16_bits(vv[0] - bf16_val(h.x));
    h.y = bf16_bits(vv[1]); l.y = bf16_bits(vv[1] - bf16_val(h.y));
    h.z = bf16_bits(vv[2]); l.z = bf16_bits(vv[2] - bf16_val(h.z));
    h.w = bf16_bits(vv[3]); l.w = bf16_bits(vv[3] - bf16_val(h.w));
    *reinterpret_cast<ushort4*>(hi + i) = h;
    *reinterpret_cast<ushort4*>(lo + i) = l;
}

// ---------------- MMA primitives ---------------------------------------------
#define MMA_BF16(ac, a, b0, b1)                                              \
    asm volatile("mma.sync.aligned.m16n8k16.row.col.f32.bf16.bf16.f32 "      \
                 "{%0,%1,%2,%3},{%4,%5,%6,%7},{%8,%9},{%0,%1,%2,%3};"        \
                 : "+f"(ac[0]), "+f"(ac[1]), "+f"(ac[2]), "+f"(ac[3])        \
                 : "r"(a[0]), "r"(a[1]), "r"(a[2]), "r"(a[3]),               \
                   "r"(b0), "r"(b1))

__device__ __forceinline__ void ldsm_x4(unsigned int* r, const unsigned short* p) {
    unsigned int sa = (unsigned int)__cvta_generic_to_shared(p);
    asm volatile("ldmatrix.sync.aligned.m8n8.x4.shared.b16 {%0,%1,%2,%3},[%4];"
                 : "=r"(r[0]), "=r"(r[1]), "=r"(r[2]), "=r"(r[3]) : "r"(sa));
}
__device__ __forceinline__ void ldsm_x4t(unsigned int* r, const unsigned short* p) {
    unsigned int sa = (unsigned int)__cvta_generic_to_shared(p);
    asm volatile("ldmatrix.sync.aligned.m8n8.x4.trans.shared.b16 {%0,%1,%2,%3},[%4];"
                 : "=r"(r[0]), "=r"(r[1]), "=r"(r[2]), "=r"(r[3]) : "r"(sa));
}
__device__ __forceinline__ void cp16(unsigned short* sdst, const unsigned short* gsrc) {
    unsigned int d = (unsigned int)__cvta_generic_to_shared(sdst);
    asm volatile("cp.async.cg.shared.global [%0], [%1], 16;" :: "r"(d), "l"(gsrc));
}
#define CP_COMMIT() asm volatile("cp.async.commit_group;" ::: "memory")
#define CP_WAIT0()  asm volatile("cp.async.wait_group 0;" ::: "memory")
#define CP_WAIT1()  asm volatile("cp.async.wait_group 1;" ::: "memory")

// ---------------- tensor-core GEMM: BM x 64 x BK32 ---------------------------
// BM=128: 8 warps (4x2), stage 59.4KB pair — the proven R8 config.
// BM=64:  4 warps (2x2), stage 38.9KB pair — fills the chip for small-N GEMMs.
#define LDA_S 40
#define LDB_S 72

template<int ACT, int OUTM, int BM>
__global__ __launch_bounds__(BM * 2)
void mma_gemm(const unsigned short* __restrict__ Ahi,
              const unsigned short* __restrict__ Alo,
              const unsigned short* __restrict__ Bhi,
              const unsigned short* __restrict__ Blo,
              const float* __restrict__ bias, float* __restrict__ C,
              unsigned short* __restrict__ Ch, unsigned short* __restrict__ Cl,
              int M, int N, int K, int ldb, int ldc) {
    constexpr int A_SZ = BM * LDA_S;
    constexpr int STG  = 2 * A_SZ + 2 * 32 * LDB_S;
    constexpr int AH = 0, AL = A_SZ, BH = 2 * A_SZ, BL = 2 * A_SZ + 32 * LDB_S;
    constexpr int MWARPS = BM / 64;            // mi-warp rows: 2 (BM128) or 1*2...
    extern __shared__ __align__(16) unsigned short smem_u[];

    const int tid = threadIdx.x, lane = tid & 31, warp = tid >> 5;
    const int wm = warp >> 1, wn = warp & 1;   // BM128: 4x2; BM64: 2x2
    const int m0 = blockIdx.y * BM, n0 = blockIdx.x * 64;
    const int ar = tid >> 1, ac = (tid & 1) * 16;

    float acc[2][4][4] = {};

    auto issue_tile = [&](int k0, int st) {
        unsigned short* base = smem_u + st * STG;
        const unsigned short* gAh = Ahi + (size_t)(m0 + ar) * K + k0 + ac;
        const unsigned short* gAl = Alo + (size_t)(m0 + ar) * K + k0 + ac;
        cp16(base + AH + ar * LDA_S + ac,     gAh);
        cp16(base + AH + ar * LDA_S + ac + 8, gAh + 8);
        cp16(base + AL + ar * LDA_S + ac,     gAl);
        cp16(base + AL + ar * LDA_S + ac + 8, gAl + 8);
        if (BM == 128) {
            const int br = tid >> 3, bc = (tid & 7) * 8;
            const size_t gb = (size_t)(k0 + br) * ldb + n0 + bc;
            cp16(base + BH + br * LDB_S + bc, Bhi + gb);
            cp16(base + BL + br * LDB_S + bc, Blo + gb);
        } else {
            const int br = tid >> 2, bc = (tid & 3) * 16;
            const size_t gb = (size_t)(k0 + br) * ldb + n0 + bc;
            cp16(base + BH + br * LDB_S + bc,     Bhi + gb);
            cp16(base + BH + br * LDB_S + bc + 8, Bhi + gb + 8);
            cp16(base + BL + br * LDB_S + bc,     Blo + gb);
            cp16(base + BL + br * LDB_S + bc + 8, Blo + gb + 8);
        }
    };

    issue_tile(0, 0);
    CP_COMMIT();

    int buf = 0;
    for (int k0 = 0; k0 < K; k0 += 32) {
        if (k0 + 32 < K) { issue_tile(k0 + 32, buf ^ 1); CP_COMMIT(); CP_WAIT1(); }
        else             { CP_WAIT0(); }
        __syncthreads();

        const unsigned short* sAh = smem_u + buf * STG + AH;
        const unsigned short* sAl = smem_u + buf * STG + AL;
        const unsigned short* sBh = smem_u + buf * STG + BH;
        const unsigned short* sBl = smem_u + buf * STG + BL;

        #pragma unroll
        for (int ks = 0; ks < 32; ks += 16) {
            unsigned int ah[2][4], al[2][4];
            #pragma unroll
            for (int mi = 0; mi < 2; mi++) {
                const int off = (wm * 32 + mi * 16 + (lane & 15)) * LDA_S
                                + ks + (lane >> 4) * 8;
                ldsm_x4(ah[mi], &sAh[off]);
                ldsm_x4(al[mi], &sAl[off]);
            }
            unsigned int bh[2][4], bl[2][4];
            #pragma unroll
            for (int p = 0; p < 2; p++) {
                const int off = (ks + (lane & 15)) * LDB_S
                                + wn * 32 + p * 16 + (lane >> 4) * 8;
                ldsm_x4t(bh[p], &sBh[off]);
                ldsm_x4t(bl[p], &sBl[off]);
            }
            #pragma unroll
            for (int mi = 0; mi < 2; mi++) {
                #pragma unroll
                for (int ni = 0; ni < 4; ni++) {
                    unsigned int bh0 = bh[ni >> 1][(ni & 1) * 2];
                    unsigned int bh1 = bh[ni >> 1][(ni & 1) * 2 + 1];
                    unsigned int bl0 = bl[ni >> 1][(ni & 1) * 2];
                    unsigned int bl1 = bl[ni >> 1][(ni & 1) * 2 + 1];
                    MMA_BF16(acc[mi][ni], ah[mi], bh0, bh1);
                    MMA_BF16(acc[mi][ni], ah[mi], bl0, bl1);
                    MMA_BF16(acc[mi][ni], al[mi], bh0, bh1);
                }
            }
        }
        __syncthreads();
        buf ^= 1;
    }

    const int grp = lane >> 2, t4 = lane & 3;
    #pragma unroll
    for (int mi = 0; mi < 2; mi++) {
        #pragma unroll
        for (int ni = 0; ni < 4; ni++) {
            int row = m0 + wm * 32 + mi * 16 + grp;
            int col = n0 + wn * 32 + ni * 8 + t4 * 2;
            #pragma unroll
            for (int hv = 0; hv < 2; hv++) {
                int r = row + hv * 8;
                #pragma unroll
                for (int cc = 0; cc < 2; cc++) {
                    int n = col + cc;
                    if (n >= N) continue;
                    float v = acc[mi][ni][hv * 2 + cc] + (bias ? bias[n] : 0.0f);
                    if (ACT == 1) v = 0.5f * v * (1.0f + erff(v * 0.70710678118654752f));
                    if (OUTM == 0) {
                        C[(size_t)r * ldc + n] = v;
                    } else {
                        unsigned short h = bf16_bits(v);
                        Ch[(size_t)r * ldc + n] = h;
                        Cl[(size_t)r * ldc + n] = bf16_bits(v - bf16_val(h));
                    }
                }
            }
        }
    }
}

#define STG128   (2*128*LDA_S + 2*32*LDB_S)
#define SMEM128  (2 * STG128 * 2)      // 59392 B
#define STG64    (2*64*LDA_S + 2*32*LDB_S)
#define SMEM64   (2 * STG64 * 2)       // 38912 B

// ---------------- tensor-core flash attention (unchanged) --------------------
#define LDK 40
#define ATT_SCALE 0.17677669529663687f
#define QKV_LD (3*DD)

template<int MODE>
__global__ __launch_bounds__(128)
void attn_mma(const unsigned short* __restrict__ Qh, const unsigned short* __restrict__ Ql,
              const unsigned short* __restrict__ Kh, const unsigned short* __restrict__ Kl,
              const unsigned short* __restrict__ Vh, const unsigned short* __restrict__ Vl,
              unsigned short* __restrict__ Oh, unsigned short* __restrict__ Ol,
              const int* __restrict__ aux) {
    const int b = blockIdx.z, h = blockIdx.y, blk = blockIdx.x;
    const int tid = threadIdx.x, lane = tid & 31, w = tid >> 5;
    const int grp = lane >> 2, t4 = lane & 3;
    const size_t rowbase = (size_t)b * TT * QKV_LD + h * DHH;
    const size_t obase   = (size_t)b * TT * DD + h * DHH;

    __shared__ __align__(16) unsigned short sQh[64*LDK], sQl[64*LDK];
    __shared__ __align__(16) unsigned short sKh[64*LDK], sKl[64*LDK];
    __shared__ __align__(16) unsigned short sVh[64*LDK], sVl[64*LDK];
    __shared__ int sMask[64];

    {
        int r = tid >> 1, cs = (tid & 1) * 16;
        size_t g = rowbase + (size_t)(blk * 64 + r) * QKV_LD + cs;
        *(uint4*)&sQh[r*LDK+cs]   = *(const uint4*)(Qh + g);
        *(uint4*)&sQh[r*LDK+cs+8] = *(const uint4*)(Qh + g + 8);
        *(uint4*)&sQl[r*LDK+cs]   = *(const uint4*)(Ql + g);
        *(uint4*)&sQl[r*LDK+cs+8] = *(const uint4*)(Ql + g + 8);
    }

    const int qi0 = blk * 64 + w * 16 + grp;
    const int qi1 = qi0 + 8;
    bool qv0 = true, qv1 = true;
    int pred = 0;
    if (MODE == 0) {
        qv0 = (g_tgt[b * TT + qi0] != 0);
        qv1 = (g_tgt[b * TT + qi1] != 0);
        pred = (tid < 64) && (g_tgt[b * TT + blk * 64 + tid] == 0);
    }
    int ext = __syncthreads_or(pred);

    unsigned int qfh[2][4], qfl[2][4];
    #pragma unroll
    for (int c = 0; c < 2; c++) {
        const int off = (w * 16 + (lane & 15)) * LDK + c * 16 + (lane >> 4) * 8;
        ldsm_x4(qfh[c], &sQh[off]);
        ldsm_x4(qfl[c], &sQl[off]);
    }

    const int nT = (MODE == 0) ? (ext ? TT / 64 : (blk + 1)) : SS / 64;

    float M0 = -FLT_MAX, M1 = -FLT_MAX, L0 = 0.0f, L1 = 0.0f;
    float O[4][4] = {};

    for (int tile = 0; tile < nT; tile++) {
        const int j0 = tile * 64;
        __syncthreads();
        {
            int r = tid >> 1, cs = (tid & 1) * 16;
            size_t g = rowbase + (size_t)(j0 + r) * QKV_LD + cs;
            *(uint4*)&sKh[r*LDK+cs]   = *(const uint4*)(Kh + g);
            *(uint4*)&sKh[r*LDK+cs+8] = *(const uint4*)(Kh + g + 8);
            *(uint4*)&sKl[r*LDK+cs]   = *(const uint4*)(Kl + g);
            *(uint4*)&sKl[r*LDK+cs+8] = *(const uint4*)(Kl + g + 8);
            *(uint4*)&sVh[r*LDK+cs]   = *(const uint4*)(Vh + g);
            *(uint4*)&sVh[r*LDK+cs+8] = *(const uint4*)(Vh + g + 8);
            *(uint4*)&sVl[r*LDK+cs]   = *(const uint4*)(Vl + g);
            *(uint4*)&sVl[r*LDK+cs+8] = *(const uint4*)(Vl + g + 8);
            if (MODE == 1 && tid < 64) sMask[tid] = aux[b * SS + j0 + tid];
        }
        __syncthreads();

        float sc[8][4] = {};
        #pragma unroll
        for (int c = 0; c < 2; c++) {
            #pragma unroll
            for (int g4 = 0; g4 < 4; g4++) {
                unsigned int kbh[4], kbl[4];
                const int off = (g4 * 16 + (lane & 15)) * LDK + c * 16 + (lane >> 4) * 8;
                ldsm_x4(kbh, &sKh[off]);
                ldsm_x4(kbl, &sKl[off]);
                MMA_BF16(sc[2*g4],   qfh[c], kbh[0], kbh[2]);
                MMA_BF16(sc[2*g4],   qfh[c], kbl[0], kbl[2]);
                MMA_BF16(sc[2*g4],   qfl[c], kbh[0], kbh[2]);
                MMA_BF16(sc[2*g4+1], qfh[c], kbh[1], kbh[3]);
                MMA_BF16(sc[2*g4+1], qfh[c], kbl[1], kbl[3]);
                MMA_BF16(sc[2*g4+1], qfl[c], kbh[1], kbh[3]);
            }
        }

        float ml0 = -FLT_MAX, ml1 = -FLT_MAX;
        #pragma unroll
        for (int f = 0; f < 8; f++) {
            const int jc = j0 + f * 8 + t4 * 2;
            bool v00, v01, v10, v11;
            if (MODE == 0) {
                v00 = qv0 && (jc     <= qi0);
                v01 = qv0 && (jc + 1 <= qi0);
                v10 = qv1 && (jc     <= qi1);
                v11 = qv1 && (jc + 1 <= qi1);
            } else {
                bool k0m = sMask[f * 8 + t4 * 2]     != 0;
                bool k1m = sMask[f * 8 + t4 * 2 + 1] != 0;
                v00 = k0m; v01 = k1m; v10 = k0m; v11 = k1m;
            }
            sc[f][0] = v00 ? sc[f][0] * ATT_SCALE : -FLT_MAX;
            sc[f][1] = v01 ? sc[f][1] * ATT_SCALE : -FLT_MAX;
            sc[f][2] = v10 ? sc[f][2] * ATT_SCALE : -FLT_MAX;
            sc[f][3] = v11 ? sc[f][3] * ATT_SCALE : -FLT_MAX;
            ml0 = fmaxf(ml0, fmaxf(sc[f][0], sc[f][1]));
            ml1 = fmaxf(ml1, fmaxf(sc[f][2], sc[f][3]));
        }
        ml0 = fmaxf(ml0, __shfl_xor_sync(0xffffffffu, ml0, 1));
        ml0 = fmaxf(ml0, __shfl_xor_sync(0xffffffffu, ml0, 2));
        ml1 = fmaxf(ml1, __shfl_xor_sync(0xffffffffu, ml1, 1));
        ml1 = fmaxf(ml1, __shfl_xor_sync(0xffffffffu, ml1, 2));

        const float mn0 = fmaxf(M0, ml0), mn1 = fmaxf(M1, ml1);
        const float corr0 = fexp2((M0 - mn0) * L2E);
        const float corr1 = fexp2((M1 - mn1) * L2E);
        L0 *= corr0; L1 *= corr1;
        #pragma unroll
        for (int ni = 0; ni < 4; ni++) {
            O[ni][0] *= corr0; O[ni][1] *= corr0;
            O[ni][2] *= corr1; O[ni][3] *= corr1;
        }

        float ls0 = 0.0f, ls1 = 0.0f;
        unsigned int aH0[8], aH1[8], aL0[8], aL1[8];
        #pragma unroll
        for (int f = 0; f < 8; f++) {
            float p0 = fexp2((sc[f][0] - mn0) * L2E);
            float p1 = fexp2((sc[f][1] - mn0) * L2E);
            float p2 = fexp2((sc[f][2] - mn1) * L2E);
            float p3 = fexp2((sc[f][3] - mn1) * L2E);
            ls0 += p0 + p1; ls1 += p2 + p3;
            unsigned short h0 = bf16_bits(p0), h1 = bf16_bits(p1);
            unsigned short h2 = bf16_bits(p2), h3 = bf16_bits(p3);
            aH0[f] = (unsigned int)h0 | ((unsigned int)h1 << 16);
            aH1[f] = (unsigned int)h2 | ((unsigned int)h3 << 16);
            aL0[f] = pack_bf16x2(p0 - bf16_val(h0), p1 - bf16_val(h1));
            aL1[f] = pack_bf16x2(p2 - bf16_val(h2), p3 - bf16_val(h3));
        }
        ls0 += __shfl_xor_sync(0xffffffffu, ls0, 1);
        ls0 += __shfl_xor_sync(0xffffffffu, ls0, 2);
        ls1 += __shfl_xor_sync(0xffffffffu, ls1, 1);
        ls1 += __shfl_xor_sync(0xffffffffu, ls1, 2);
        L0 += ls0; L1 += ls1;
        M0 = mn0; M1 = mn1;

        #pragma unroll
        for (int kc = 0; kc < 4; kc++) {
            unsigned int pah[4] = { aH0[2*kc], aH1[2*kc], aH0[2*kc+1], aH1[2*kc+1] };
            unsigned int pal[4] = { aL0[2*kc], aL1[2*kc], aL0[2*kc+1], aL1[2*kc+1] };
            #pragma unroll
            for (int ph = 0; ph < 2; ph++) {
                unsigned int vbh[4], vbl[4];
                const int off = (kc * 16 + (lane & 15)) * LDK + ph * 16 + (lane >> 4) * 8;
                ldsm_x4t(vbh, &sVh[off]);
                ldsm_x4t(vbl, &sVl[off]);
                #pragma unroll
                for (int j = 0; j < 2; j++) {
                    const int ni = ph * 2 + j;
                    MMA_BF16(O[ni], pah, vbh[2*j], vbh[2*j+1]);
                    MMA_BF16(O[ni], pah, vbl[2*j], vbl[2*j+1]);
                    MMA_BF16(O[ni], pal, vbh[2*j], vbh[2*j+1]);
                }
            }
        }
    }

    const float inv0 = 1.0f / L0, inv1 = 1.0f / L1;
    const size_t o0 = obase + (size_t)qi0 * DD;
    const size_t o1 = obase + (size_t)qi1 * DD;
    #pragma unroll
    for (int ni = 0; ni < 4; ni++) {
        const int n = ni * 8 + t4 * 2;
        float v00 = O[ni][0] * inv0, v01 = O[ni][1] * inv0;
        float v10 = O[ni][2] * inv1, v11 = O[ni][3] * inv1;
        unsigned short h;
        h = bf16_bits(v00); Oh[o0 + n]     = h; Ol[o0 + n]     = bf16_bits(v00 - bf16_val(h));
        h = bf16_bits(v01); Oh[o0 + n + 1] = h; Ol[o0 + n + 1] = bf16_bits(v01 - bf16_val(h));
        h = bf16_bits(v10); Oh[o1 + n]     = h; Ol[o1 + n]     = bf16_bits(v10 - bf16_val(h));
        h = bf16_bits(v11); Oh[o1 + n + 1] = h; Ol[o1 + n + 1] = bf16_bits(v11 - bf16_val(h));
    }
}

// ---------------- residual + layernorm (+ hi/lo split) -----------------------
__global__ __launch_bounds__(128)
void ln_kernel(const float* __restrict__ x, const float* __restrict__ h,
               const float* __restrict__ g, const float* __restrict__ bvec,
               float* __restrict__ y,
               unsigned short* __restrict__ yh, unsigned short* __restrict__ yl) {
    int row = blockIdx.x * 4 + (threadIdx.x >> 5);
    int lane = threadIdx.x & 31;
    const float* xr = x + (size_t)row * DD;
    const float* hr = h + (size_t)row * DD;
    float vals[8];
    float s = 0.0f;
    #pragma unroll
    for (int u = 0; u < 8; u++) {
        int c = lane + u * 32;
        vals[u] = xr[c] + hr[c];
        s += vals[u];
    }
    #pragma unroll
    for (int off = 16; off > 0; off >>= 1) s += __shfl_xor_sync(0xffffffffu, s, off);
    float mean = s * (1.0f / DD);
    float vs = 0.0f;
    #pragma unroll
    for (int u = 0; u < 8; u++) { float d = vals[u] - mean; vs += d * d; }
    #pragma unroll
    for (int off = 16; off > 0; off >>= 1) vs += __shfl_xor_sync(0xffffffffu, vs, off);
    float inv = rsqrtf(vs * (1.0f / DD) + 1e-5f);
    float* yr = y + (size_t)row * DD;
    #pragma unroll
    for (int u = 0; u < 8; u++) {
        int c = lane + u * 32;
        float v = (vals[u] - mean) * inv * g[c] + bvec[c];
        yr[c] = v;
        unsigned short hb = bf16_bits(v);
        yh[(size_t)row * DD + c] = hb;
        yl[(size_t)row * DD + c] = bf16_bits(v - bf16_val(hb));
    }
}

// ---------------- launch -----------------------------------------------------
extern "C" void kernel_launch(void* const* d_in, const int* in_sizes, int n_in,
                              void* d_out, int out_size) {
    const float* src_embedded = (const float*)d_in[0];
    const int*   src_mask     = (const int*)d_in[1];
    const void*  tgt_raw      = d_in[2];
    const float* emb   = (const float*)d_in[3];
    const float* pe    = (const float*)d_in[4];
    const float* sa_wq = (const float*)d_in[5];
    const float* sa_wk = (const float*)d_in[6];
    const float* sa_wv = (const float*)d_in[7];
    const float* sa_wo = (const float*)d_in[8];
    const float* sa_bo = (const float*)d_in[9];
    const float* ca_wq = (const float*)d_in[10];
    const float* ca_wk = (const float*)d_in[11];
    const float* ca_wv = (const float*)d_in[12];
    const float* ca_wo = (const float*)d_in[13];
    const float* ca_bo = (const float*)d_in[14];
    const float* ln1_g = (const float*)d_in[15];
    const float* ln1_b = (const float*)d_in[16];
    const float* ln2_g = (const float*)d_in[17];
    const float* ln2_b = (const float*)d_in[18];
    const float* ln3_g = (const float*)d_in[19];
    const float* ln3_b = (const float*)d_in[20];
    const float* fc1_w = (const float*)d_in[21];
    const float* fc1_b = (const float*)d_in[22];
    const float* fc2_w = (const float*)d_in[23];
    const float* fc2_b = (const float*)d_in[24];
    const float* out_w = (const float*)d_in[25];
    const float* out_b = (const float*)d_in[26];

    float *x0, *pr, *x1, *x2, *x3;
    unsigned short *xh, *xl, *eh, *el, *qkvh, *qkvl, *ath, *atl, *ahi, *alo, *bhi, *blo;
    cudaGetSymbolAddress((void**)&x0,   g_x0);
    cudaGetSymbolAddress((void**)&pr,   g_pr);
    cudaGetSymbolAddress((void**)&x1,   g_x1);
    cudaGetSymbolAddress((void**)&x2,   g_x2);
    cudaGetSymbolAddress((void**)&x3,   g_x3);
    cudaGetSymbolAddress((void**)&xh,   g_xh);
    cudaGetSymbolAddress((void**)&xl,   g_xl);
    cudaGetSymbolAddress((void**)&eh,   g_eh);
    cudaGetSymbolAddress((void**)&el,   g_el);
    cudaGetSymbolAddress((void**)&qkvh, g_qkvh);
    cudaGetSymbolAddress((void**)&qkvl, g_qkvl);
    cudaGetSymbolAddress((void**)&ath,  g_ath);
    cudaGetSymbolAddress((void**)&atl,  g_atl);
    cudaGetSymbolAddress((void**)&ahi,  g_ahi);
    cudaGetSymbolAddress((void**)&alo,  g_alo);
    cudaGetSymbolAddress((void**)&bhi,  g_bhi);
    cudaGetSymbolAddress((void**)&blo,  g_blo);

    cudaFuncSetAttribute(mma_gemm<0,0,128>, cudaFuncAttributeMaxDynamicSharedMemorySize, SMEM128);
    cudaFuncSetAttribute(mma_gemm<1,1,128>, cudaFuncAttributeMaxDynamicSharedMemorySize, SMEM128);
    cudaFuncSetAttribute(mma_gemm<0,1,64>,  cudaFuncAttributeMaxDynamicSharedMemorySize, SMEM64);
    cudaFuncSetAttribute(mma_gemm<0,0,64>,  cudaFuncAttributeMaxDynamicSharedMemorySize, SMEM64);

    float* outp   = (float*)d_out;
    float* logits = outp;
    float* tgt_out = nullptr;
    long long need = (long long)NROWS * NVOCAB;
    if ((long long)out_size >= need + NROWS) tgt_out = outp + need;

    dim3 gD64(DD / 64, NROWS / 64);                // (4, 64)  = 256 blocks
    dim3 gQKV64((3 * DD) / 64, NROWS / 64);        // (12, 64) = 768 blocks
    dim3 gKV64((2 * DD) / 64, NROWS / 64);         // (8, 64)  = 512 blocks
    dim3 gF(NDFF / 64, NROWS / 128);               // (32, 32) = 1024 blocks
    dim3 gV(NVPAD / 64, NROWS / 128);              // (398, 32)
    dim3 gAttn(TT / 64, HH, BB);
    const int WB = 256;

    // launch order puts the QKV GEMM at ncu slot 6 (-s 5 -c 1)
    prep_tgt_kernel<<<(NROWS + 127) / 128, 128>>>(tgt_raw, tgt_out);          // 1
    embed_kernel<<<(NROWS * DD) / 256, 256>>>(emb, pe);                       // 2
    conv_w4<<<(DD*DD)/(4*WB), WB>>>(sa_wq, bhi, blo, DD, DD, 3*DD, 0);        // 3
    conv_w4<<<(DD*DD)/(4*WB), WB>>>(sa_wk, bhi, blo, DD, DD, 3*DD, DD);       // 4
    conv_w4<<<(DD*DD)/(4*WB), WB>>>(sa_wv, bhi, blo, DD, DD, 3*DD, 2*DD);     // 5
    mma_gemm<0,1,64><<<gQKV64, 128, SMEM64>>>(xh, xl, bhi, blo, nullptr, nullptr,
                                              qkvh, qkvl, NROWS, 3*DD, DD, 3*DD, 3*DD); // 6
    attn_mma<0><<<gAttn, 128>>>(qkvh, qkvl, qkvh + DD, qkvl + DD,
                                qkvh + 2*DD, qkvl + 2*DD, ath, atl, nullptr);
    conv_w4<<<(DD*DD)/(4*WB), WB>>>(sa_wo, bhi, blo, DD, DD, DD, 0);
    mma_gemm<0,0,64><<<gD64, 128, SMEM64>>>(ath, atl, bhi, blo, sa_bo, pr,
                                            nullptr, nullptr, NROWS, DD, DD, DD, DD);
    ln_kernel<<<NROWS / 4, 128>>>(x0, pr, ln1_g, ln1_b, x1, xh, xl);

    // ---- cross-attention block ----
    encmask_kernel<<<(NROWS * DD) / 256, 256>>>(src_embedded, src_mask);
    conv_w4<<<(DD*DD)/(4*WB), WB>>>(ca_wq, bhi, blo, DD, DD, DD, 0);
    mma_gemm<0,1,64><<<gD64, 128, SMEM64>>>(xh, xl, bhi, blo, nullptr, nullptr,
                                            qkvh, qkvl, NROWS, DD, DD, DD, 3*DD);
    conv_w4<<<(DD*DD)/(4*WB), WB>>>(ca_wk, bhi, blo, DD, DD, 2*DD, 0);
    conv_w4<<<(DD*DD)/(4*WB), WB>>>(ca_wv, bhi, blo, DD, DD, 2*DD, DD);
    mma_gemm<0,1,64><<<gKV64, 128, SMEM64>>>(eh, el, bhi, blo, nullptr, nullptr,
                                             qkvh + DD, qkvl + DD, NROWS, 2*DD, DD, 2*DD, 3*DD);
    attn_mma<1><<<gAttn, 128>>>(qkvh, qkvl, qkvh + DD, qkvl + DD,
                                qkvh + 2*DD, qkvl + 2*DD, ath, atl, src_mask);
    conv_w4<<<(DD*DD)/(4*WB), WB>>>(ca_wo, bhi, blo, DD, DD, DD, 0);
    mma_gemm<0,0,64><<<gD64, 128, SMEM64>>>(ath, atl, bhi, blo, ca_bo, pr,
                                            nullptr, nullptr, NROWS, DD, DD, DD, DD);
    ln_kernel<<<NROWS / 4, 128>>>(x1, pr, ln2_g, ln2_b, x2, xh, xl);

    // ---- FFN ----
    conv_w4<<<(DD*NDFF)/(4*WB), WB>>>(fc1_w, bhi, blo, DD, NDFF, NDFF, 0);
    mma_gemm<1,1,128><<<gF, 256, SMEM128>>>(xh, xl, bhi, blo, fc1_b, nullptr,
                                            ahi, alo, NROWS, NDFF, DD, NDFF, NDFF);
    conv_w4<<<(NDFF*DD)/(4*WB), WB>>>(fc2_w, bhi, blo, NDFF, DD, DD, 0);
    mma_gemm<0,0,64><<<gD64, 128, SMEM64>>>(ahi, alo, bhi, blo, fc2_b, pr,
                                            nullptr, nullptr, NROWS, DD, NDFF, DD, DD);
    ln_kernel<<<NROWS / 4, 128>>>(x2, pr, ln3_g, ln3_b, x3, xh, xl);

    // ---- vocab projection ----
    conv_split_pad4<<<(DD*NVPAD)/(4*WB), WB>>>(out_w, bhi, blo, DD, NVOCAB, NVPAD);
    mma_gemm<0,0,128><<<gV, 256, SMEM128>>>(xh, xl, bhi, blo, out_b, logits,
                                            nullptr, nullptr, NROWS, NVOCAB, DD, NVPAD, NVOCAB);
}

// round 14
// speedup vs baseline: 1.4403x; 1.3071x over previous
#include <cuda_runtime.h>
#include <cuda_bf16.h>
#include <cuda_fp16.h>
#include <cstdint>
#include <cstdio>
#include <math.h>
#include <float.h>

#define BB 2
#define SS 2048
#define TT 2048
#define NVOCAB 25426
#define NVPAD 25472
#define DD 256
#define HH 8
#define DHH 32
#define NDFF 2048
#define NROWS (BB*TT)
#define T0LEN (TT-1)

// ---------------- scratch ----------------------------------------------------
static __device__ float g_x0 [NROWS*DD];
static __device__ float g_pr [NROWS*DD];
static __device__ float g_x1 [NROWS*DD];
static __device__ float g_x2 [NROWS*DD];
static __device__ float g_x3 [NROWS*DD];
static __device__ int   g_tgt[NROWS];
// bf16 hi/lo buffers (xh doubles as fp16 buffer after LN3)
static __device__ unsigned short g_xh [NROWS*DD],   g_xl [NROWS*DD];
static __device__ unsigned short g_eh [NROWS*DD],   g_el [NROWS*DD];
static __device__ unsigned short g_qkvh[NROWS*3*DD], g_qkvl[NROWS*3*DD];
static __device__ unsigned short g_ath[NROWS*DD],   g_atl[NROWS*DD];
static __device__ unsigned short g_ahi[NROWS*NDFF], g_alo[NROWS*NDFF];
static __device__ unsigned short g_bhi[DD*NVPAD],   g_blo[DD*NVPAD];

// ---------------- helpers ----------------------------------------------------
__device__ __forceinline__ unsigned short bf16_bits(float v) {
    return (unsigned short)__bfloat16_as_ushort(__float2bfloat16(v));
}
__device__ __forceinline__ float bf16_val(unsigned short u) {
    return __bfloat162float(__ushort_as_bfloat16(u));
}
__device__ __forceinline__ unsigned short fp16_bits(float v) {
    return (unsigned short)__half_as_ushort(__float2half_rn(v));
}
__device__ __forceinline__ unsigned int pack_bf16x2(float lo, float hi) {
    unsigned int r;
    asm("cvt.rn.bf16x2.f32 %0, %1, %2;" : "=r"(r) : "f"(hi), "f"(lo));
    return r;
}
__device__ __forceinline__ float fexp2(float t) {
    t = fmaxf(t, -126.0f);
    float z  = t + 12582912.0f;
    float fi = z - 12582912.0f;
    float f  = t - fi;
    int   ii = __float_as_int(z) - 0x4B400000;
    float p = 1.54035304e-4f;
    p = fmaf(p, f, 1.33335581e-3f);
    p = fmaf(p, f, 9.61812910e-3f);
    p = fmaf(p, f, 5.55041087e-2f);
    p = fmaf(p, f, 2.40226507e-1f);
    p = fmaf(p, f, 6.93147181e-1f);
    p = fmaf(p, f, 1.0f);
    return __int_as_float(__float_as_int(p) + (ii << 23));
}
#define L2E 1.4426950408889634f

// ---------------- prep kernels -----------------------------------------------
__global__ void prep_tgt_kernel(const void* __restrict__ tgt_raw,
                                float* __restrict__ tgt_out) {
    __shared__ int s_odd;
    if (threadIdx.x == 0) s_odd = 0;
    __syncthreads();
    const int* raw = (const int*)tgt_raw;
    int local = 0;
    for (int i = threadIdx.x; i < BB * T0LEN; i += blockDim.x)
        if ((i & 1) && raw[i] != 0) local = 1;
    if (local) atomicOr(&s_odd, 1);
    __syncthreads();
    int is64 = s_odd ? 0 : 1;

    int idx = blockIdx.x * blockDim.x + threadIdx.x;
    if (idx >= NROWS) return;
    int b = idx / TT, t = idx % TT;
    int id;
    if (t == 0) id = NVOCAB;
    else {
        size_t src = (size_t)b * T0LEN + (t - 1);
        if (is64) id = (int)((const long long*)tgt_raw)[src];
        else      id = ((const int*)tgt_raw)[src];
    }
    if (id < 0) id = 0;
    if (id > NVOCAB) id = NVOCAB;
    g_tgt[idx] = id;
    if (tgt_out) tgt_out[idx] = (t == 0) ? 0.0f : (float)id;
}

__global__ void embed_kernel(const float* __restrict__ emb,
                             const float* __restrict__ pe) {
    int idx = blockIdx.x * blockDim.x + threadIdx.x;
    if (idx >= NROWS * DD) return;
    int row = idx >> 8, d = idx & 255, t = row & (TT - 1);
    int id = g_tgt[row];
    float v = 2.0f * emb[(size_t)id * DD + d] + pe[(size_t)t * DD + d];
    g_x0[idx] = v;
    unsigned short h = bf16_bits(v);
    g_xh[idx] = h;
    g_xl[idx] = bf16_bits(v - bf16_val(h));
}

__global__ void encmask_kernel(const float* __restrict__ src,
                               const int* __restrict__ mask) {
    int idx = blockIdx.x * blockDim.x + threadIdx.x;
    if (idx >= NROWS * DD) return;
    float v = mask[idx >> 8] ? src[idx] : 0.0f;
    unsigned short h = bf16_bits(v);
    g_eh[idx] = h;
    g_el[idx] = bf16_bits(v - bf16_val(h));
}

__global__ void conv_w4(const float* __restrict__ x,
                        unsigned short* __restrict__ hi,
                        unsigned short* __restrict__ lo,
                        int K, int N, int ldb, int col0) {
    int i = (blockIdx.x * blockDim.x + threadIdx.x) * 4;
    if (i >= K * N) return;
    int r = i / N, c = i % N;
    float4 v = *reinterpret_cast<const float4*>(x + (size_t)r * N + c);
    ushort4 h, l;
    h.x = bf16_bits(v.x); l.x = bf16_bits(v.x - bf16_val(h.x));
    h.y = bf16_bits(v.y); l.y = bf16_bits(v.y - bf16_val(h.y));
    h.z = bf16_bits(v.z); l.z = bf16_bits(v.z - bf16_val(h.z));
    h.w = bf16_bits(v.w); l.w = bf16_bits(v.w - bf16_val(h.w));
    size_t dst = (size_t)r * ldb + col0 + c;
    *reinterpret_cast<ushort4*>(hi + dst) = h;
    *reinterpret_cast<ushort4*>(lo + dst) = l;
}

// fp16 pad convert (single array, zero pad to ldb)
__global__ void conv_pad_h4(const float* __restrict__ x,
                            unsigned short* __restrict__ hi,
                            int K, int N, int ldb) {
    int i = (blockIdx.x * blockDim.x + threadIdx.x) * 4;
    if (i >= K * ldb) return;
    int r = i / ldb, c = i % ldb;
    ushort4 h;
    float vv[4];
    #pragma unroll
    for (int j = 0; j < 4; j++) {
        int cc = c + j;
        vv[j] = (cc < N) ? x[(size_t)r * N + cc] : 0.0f;
    }
    h.x = fp16_bits(vv[0]); h.y = fp16_bits(vv[1]);
    h.z = fp16_bits(vv[2]); h.w = fp16_bits(vv[3]);
    *reinterpret_cast<ushort4*>(hi + i) = h;
}

// ---------------- MMA primitives ---------------------------------------------
#define MMA_BF16(ac, a, b0, b1)                                              \
    asm volatile("mma.sync.aligned.m16n8k16.row.col.f32.bf16.bf16.f32 "      \
                 "{%0,%1,%2,%3},{%4,%5,%6,%7},{%8,%9},{%0,%1,%2,%3};"        \
                 : "+f"(ac[0]), "+f"(ac[1]), "+f"(ac[2]), "+f"(ac[3])        \
                 : "r"(a[0]), "r"(a[1]), "r"(a[2]), "r"(a[3]),               \
                   "r"(b0), "r"(b1))

#define MMA_F16(ac, a, b0, b1)                                               \
    asm volatile("mma.sync.aligned.m16n8k16.row.col.f32.f16.f16.f32 "        \
                 "{%0,%1,%2,%3},{%4,%5,%6,%7},{%8,%9},{%0,%1,%2,%3};"        \
                 : "+f"(ac[0]), "+f"(ac[1]), "+f"(ac[2]), "+f"(ac[3])        \
                 : "r"(a[0]), "r"(a[1]), "r"(a[2]), "r"(a[3]),               \
                   "r"(b0), "r"(b1))

__device__ __forceinline__ void ldsm_x4(unsigned int* r, const unsigned short* p) {
    unsigned int sa = (unsigned int)__cvta_generic_to_shared(p);
    asm volatile("ldmatrix.sync.aligned.m8n8.x4.shared.b16 {%0,%1,%2,%3},[%4];"
                 : "=r"(r[0]), "=r"(r[1]), "=r"(r[2]), "=r"(r[3]) : "r"(sa));
}
__device__ __forceinline__ void ldsm_x4t(unsigned int* r, const unsigned short* p) {
    unsigned int sa = (unsigned int)__cvta_generic_to_shared(p);
    asm volatile("ldmatrix.sync.aligned.m8n8.x4.trans.shared.b16 {%0,%1,%2,%3},[%4];"
                 : "=r"(r[0]), "=r"(r[1]), "=r"(r[2]), "=r"(r[3]) : "r"(sa));
}
__device__ __forceinline__ void cp16(unsigned short* sdst, const unsigned short* gsrc) {
    unsigned int d = (unsigned int)__cvta_generic_to_shared(sdst);
    asm volatile("cp.async.cg.shared.global [%0], [%1], 16;" :: "r"(d), "l"(gsrc));
}
#define CP_COMMIT() asm volatile("cp.async.commit_group;" ::: "memory")
#define CP_WAIT0()  asm volatile("cp.async.wait_group 0;" ::: "memory")
#define CP_WAIT1()  asm volatile("cp.async.wait_group 1;" ::: "memory")

// ---------------- tensor-core GEMM (bf16 split, BM template) -----------------
#define LDA_S 40
#define LDB_S 72

template<int ACT, int OUTM, int BM>
__global__ __launch_bounds__(BM * 2)
void mma_gemm(const unsigned short* __restrict__ Ahi,
              const unsigned short* __restrict__ Alo,
              const unsigned short* __restrict__ Bhi,
              const unsigned short* __restrict__ Blo,
              const float* __restrict__ bias, float* __restrict__ C,
              unsigned short* __restrict__ Ch, unsigned short* __restrict__ Cl,
              int M, int N, int K, int ldb, int ldc) {
    constexpr int A_SZ = BM * LDA_S;
    constexpr int STG  = 2 * A_SZ + 2 * 32 * LDB_S;
    constexpr int AH = 0, AL = A_SZ, BH = 2 * A_SZ, BL = 2 * A_SZ + 32 * LDB_S;
    extern __shared__ __align__(16) unsigned short smem_u[];

    const int tid = threadIdx.x, lane = tid & 31, warp = tid >> 5;
    const int wm = warp >> 1, wn = warp & 1;
    const int m0 = blockIdx.y * BM, n0 = blockIdx.x * 64;
    const int ar = tid >> 1, ac = (tid & 1) * 16;

    float acc[2][4][4] = {};

    auto issue_tile = [&](int k0, int st) {
        unsigned short* base = smem_u + st * STG;
        const unsigned short* gAh = Ahi + (size_t)(m0 + ar) * K + k0 + ac;
        const unsigned short* gAl = Alo + (size_t)(m0 + ar) * K + k0 + ac;
        cp16(base + AH + ar * LDA_S + ac,     gAh);
        cp16(base + AH + ar * LDA_S + ac + 8, gAh + 8);
        cp16(base + AL + ar * LDA_S + ac,     gAl);
        cp16(base + AL + ar * LDA_S + ac + 8, gAl + 8);
        if (BM == 128) {
            const int br = tid >> 3, bc = (tid & 7) * 8;
            const size_t gb = (size_t)(k0 + br) * ldb + n0 + bc;
            cp16(base + BH + br * LDB_S + bc, Bhi + gb);
            cp16(base + BL + br * LDB_S + bc, Blo + gb);
        } else {
            const int br = tid >> 2, bc = (tid & 3) * 16;
            const size_t gb = (size_t)(k0 + br) * ldb + n0 + bc;
            cp16(base + BH + br * LDB_S + bc,     Bhi + gb);
            cp16(base + BH + br * LDB_S + bc + 8, Bhi + gb + 8);
            cp16(base + BL + br * LDB_S + bc,     Blo + gb);
            cp16(base + BL + br * LDB_S + bc + 8, Blo + gb + 8);
        }
    };

    issue_tile(0, 0);
    CP_COMMIT();

    int buf = 0;
    for (int k0 = 0; k0 < K; k0 += 32) {
        if (k0 + 32 < K) { issue_tile(k0 + 32, buf ^ 1); CP_COMMIT(); CP_WAIT1(); }
        else             { CP_WAIT0(); }
        __syncthreads();

        const unsigned short* sAh = smem_u + buf * STG + AH;
        const unsigned short* sAl = smem_u + buf * STG + AL;
        const unsigned short* sBh = smem_u + buf * STG + BH;
        const unsigned short* sBl = smem_u + buf * STG + BL;

        #pragma unroll
        for (int ks = 0; ks < 32; ks += 16) {
            unsigned int ah[2][4], al[2][4];
            #pragma unroll
            for (int mi = 0; mi < 2; mi++) {
                const int off = (wm * 32 + mi * 16 + (lane & 15)) * LDA_S
                                + ks + (lane >> 4) * 8;
                ldsm_x4(ah[mi], &sAh[off]);
                ldsm_x4(al[mi], &sAl[off]);
            }
            unsigned int bh[2][4], bl[2][4];
            #pragma unroll
            for (int p = 0; p < 2; p++) {
                const int off = (ks + (lane & 15)) * LDB_S
                                + wn * 32 + p * 16 + (lane >> 4) * 8;
                ldsm_x4t(bh[p], &sBh[off]);
                ldsm_x4t(bl[p], &sBl[off]);
            }
            #pragma unroll
            for (int mi = 0; mi < 2; mi++) {
                #pragma unroll
                for (int ni = 0; ni < 4; ni++) {
                    unsigned int bh0 = bh[ni >> 1][(ni & 1) * 2];
                    unsigned int bh1 = bh[ni >> 1][(ni & 1) * 2 + 1];
                    unsigned int bl0 = bl[ni >> 1][(ni & 1) * 2];
                    unsigned int bl1 = bl[ni >> 1][(ni & 1) * 2 + 1];
                    MMA_BF16(acc[mi][ni], ah[mi], bh0, bh1);
                    MMA_BF16(acc[mi][ni], ah[mi], bl0, bl1);
                    MMA_BF16(acc[mi][ni], al[mi], bh0, bh1);
                }
            }
        }
        __syncthreads();
        buf ^= 1;
    }

    const int grp = lane >> 2, t4 = lane & 3;
    #pragma unroll
    for (int mi = 0; mi < 2; mi++) {
        #pragma unroll
        for (int ni = 0; ni < 4; ni++) {
            int row = m0 + wm * 32 + mi * 16 + grp;
            int col = n0 + wn * 32 + ni * 8 + t4 * 2;
            #pragma unroll
            for (int hv = 0; hv < 2; hv++) {
                int r = row + hv * 8;
                #pragma unroll
                for (int cc = 0; cc < 2; cc++) {
                    int n = col + cc;
                    if (n >= N) continue;
                    float v = acc[mi][ni][hv * 2 + cc] + (bias ? bias[n] : 0.0f);
                    if (ACT == 1) v = 0.5f * v * (1.0f + erff(v * 0.70710678118654752f));
                    if (OUTM == 0) {
                        C[(size_t)r * ldc + n] = v;
                    } else {
                        unsigned short h = bf16_bits(v);
                        Ch[(size_t)r * ldc + n] = h;
                        Cl[(size_t)r * ldc + n] = bf16_bits(v - bf16_val(h));
                    }
                }
            }
        }
    }
}

#define STG128   (2*128*LDA_S + 2*32*LDB_S)
#define SMEM128  (2 * STG128 * 2)
#define STG64    (2*64*LDA_S + 2*32*LDB_S)
#define SMEM64   (2 * STG64 * 2)

// ---------------- fp16 single-pass GEMM (vocab): BM128 x BN64 x BK32 --------
#define STG_H  (128*LDA_S + 32*LDB_S)      // 7424 ushorts
#define SMEM_H (2 * STG_H * 2)             // 29696 B

__global__ __launch_bounds__(256)
void mma_gemm_h(const unsigned short* __restrict__ Ah,
                const unsigned short* __restrict__ Bh,
                const float* __restrict__ bias, float* __restrict__ C,
                int M, int N, int K, int ldb, int ldc) {
    constexpr int AH = 0, BH = 128 * LDA_S;
    extern __shared__ __align__(16) unsigned short smem_u[];

    const int tid = threadIdx.x, lane = tid & 31, warp = tid >> 5;
    const int wm = warp >> 1, wn = warp & 1;
    const int m0 = blockIdx.y * 128, n0 = blockIdx.x * 64;
    const int ar = tid >> 1, ac = (tid & 1) * 16;
    const int br = tid >> 3, bc = (tid & 7) * 8;

    float acc[2][4][4] = {};

    auto issue_tile = [&](int k0, int st) {
        unsigned short* base = smem_u + st * STG_H;
        const unsigned short* gA = Ah + (size_t)(m0 + ar) * K + k0 + ac;
        cp16(base + AH + ar * LDA_S + ac,     gA);
        cp16(base + AH + ar * LDA_S + ac + 8, gA + 8);
        const size_t gb = (size_t)(k0 + br) * ldb + n0 + bc;
        cp16(base + BH + br * LDB_S + bc, Bh + gb);
    };

    issue_tile(0, 0);
    CP_COMMIT();

    int buf = 0;
    for (int k0 = 0; k0 < K; k0 += 32) {
        if (k0 + 32 < K) { issue_tile(k0 + 32, buf ^ 1); CP_COMMIT(); CP_WAIT1(); }
        else             { CP_WAIT0(); }
        __syncthreads();

        const unsigned short* sA = smem_u + buf * STG_H + AH;
        const unsigned short* sB = smem_u + buf * STG_H + BH;

        #pragma unroll
        for (int ks = 0; ks < 32; ks += 16) {
            unsigned int a[2][4];
            #pragma unroll
            for (int mi = 0; mi < 2; mi++) {
                const int off = (wm * 32 + mi * 16 + (lane & 15)) * LDA_S
                                + ks + (lane >> 4) * 8;
                ldsm_x4(a[mi], &sA[off]);
            }
            unsigned int b[2][4];
            #pragma unroll
            for (int p = 0; p < 2; p++) {
                const int off = (ks + (lane & 15)) * LDB_S
                                + wn * 32 + p * 16 + (lane >> 4) * 8;
                ldsm_x4t(b[p], &sB[off]);
            }
            #pragma unroll
            for (int mi = 0; mi < 2; mi++) {
                #pragma unroll
                for (int ni = 0; ni < 4; ni++) {
                    unsigned int b0 = b[ni >> 1][(ni & 1) * 2];
                    unsigned int b1 = b[ni >> 1][(ni & 1) * 2 + 1];
                    MMA_F16(acc[mi][ni], a[mi], b0, b1);
                }
            }
        }
        __syncthreads();
        buf ^= 1;
    }

    const int grp = lane >> 2, t4 = lane & 3;
    #pragma unroll
    for (int mi = 0; mi < 2; mi++) {
        #pragma unroll
        for (int ni = 0; ni < 4; ni++) {
            int row = m0 + wm * 32 + mi * 16 + grp;
            int col = n0 + wn * 32 + ni * 8 + t4 * 2;
            #pragma unroll
            for (int hv = 0; hv < 2; hv++) {
                int r = row + hv * 8;
                #pragma unroll
                for (int cc = 0; cc < 2; cc++) {
                    int n = col + cc;
                    if (n >= N) continue;
                    C[(size_t)r * ldc + n] = acc[mi][ni][hv * 2 + cc] + bias[n];
                }
            }
        }
    }
}

// ---------------- tensor-core flash attention (unchanged) --------------------
#define LDK 40
#define ATT_SCALE 0.17677669529663687f
#define QKV_LD (3*DD)

template<int MODE>
__global__ __launch_bounds__(128)
void attn_mma(const unsigned short* __restrict__ Qh, const unsigned short* __restrict__ Ql,
              const unsigned short* __restrict__ Kh, const unsigned short* __restrict__ Kl,
              const unsigned short* __restrict__ Vh, const unsigned short* __restrict__ Vl,
              unsigned short* __restrict__ Oh, unsigned short* __restrict__ Ol,
              const int* __restrict__ aux) {
    const int b = blockIdx.z, h = blockIdx.y, blk = blockIdx.x;
    const int tid = threadIdx.x, lane = tid & 31, w = tid >> 5;
    const int grp = lane >> 2, t4 = lane & 3;
    const size_t rowbase = (size_t)b * TT * QKV_LD + h * DHH;
    const size_t obase   = (size_t)b * TT * DD + h * DHH;

    __shared__ __align__(16) unsigned short sQh[64*LDK], sQl[64*LDK];
    __shared__ __align__(16) unsigned short sKh[64*LDK], sKl[64*LDK];
    __shared__ __align__(16) unsigned short sVh[64*LDK], sVl[64*LDK];
    __shared__ int sMask[64];

    {
        int r = tid >> 1, cs = (tid & 1) * 16;
        size_t g = rowbase + (size_t)(blk * 64 + r) * QKV_LD + cs;
        *(uint4*)&sQh[r*LDK+cs]   = *(const uint4*)(Qh + g);
        *(uint4*)&sQh[r*LDK+cs+8] = *(const uint4*)(Qh + g + 8);
        *(uint4*)&sQl[r*LDK+cs]   = *(const uint4*)(Ql + g);
        *(uint4*)&sQl[r*LDK+cs+8] = *(const uint4*)(Ql + g + 8);
    }

    const int qi0 = blk * 64 + w * 16 + grp;
    const int qi1 = qi0 + 8;
    bool qv0 = true, qv1 = true;
    int pred = 0;
    if (MODE == 0) {
        qv0 = (g_tgt[b * TT + qi0] != 0);
        qv1 = (g_tgt[b * TT + qi1] != 0);
        pred = (tid < 64) && (g_tgt[b * TT + blk * 64 + tid] == 0);
    }
    int ext = __syncthreads_or(pred);

    unsigned int qfh[2][4], qfl[2][4];
    #pragma unroll
    for (int c = 0; c < 2; c++) {
        const int off = (w * 16 + (lane & 15)) * LDK + c * 16 + (lane >> 4) * 8;
        ldsm_x4(qfh[c], &sQh[off]);
        ldsm_x4(qfl[c], &sQl[off]);
    }

    const int nT = (MODE == 0) ? (ext ? TT / 64 : (blk + 1)) : SS / 64;

    float M0 = -FLT_MAX, M1 = -FLT_MAX, L0 = 0.0f, L1 = 0.0f;
    float O[4][4] = {};

    for (int tile = 0; tile < nT; tile++) {
        const int j0 = tile * 64;
        __syncthreads();
        {
            int r = tid >> 1, cs = (tid & 1) * 16;
            size_t g = rowbase + (size_t)(j0 + r) * QKV_LD + cs;
            *(uint4*)&sKh[r*LDK+cs]   = *(const uint4*)(Kh + g);
            *(uint4*)&sKh[r*LDK+cs+8] = *(const uint4*)(Kh + g + 8);
            *(uint4*)&sKl[r*LDK+cs]   = *(const uint4*)(Kl + g);
            *(uint4*)&sKl[r*LDK+cs+8] = *(const uint4*)(Kl + g + 8);
            *(uint4*)&sVh[r*LDK+cs]   = *(const uint4*)(Vh + g);
            *(uint4*)&sVh[r*LDK+cs+8] = *(const uint4*)(Vh + g + 8);
            *(uint4*)&sVl[r*LDK+cs]   = *(const uint4*)(Vl + g);
            *(uint4*)&sVl[r*LDK+cs+8] = *(const uint4*)(Vl + g + 8);
            if (MODE == 1 && tid < 64) sMask[tid] = aux[b * SS + j0 + tid];
        }
        __syncthreads();

        float sc[8][4] = {};
        #pragma unroll
        for (int c = 0; c < 2; c++) {
            #pragma unroll
            for (int g4 = 0; g4 < 4; g4++) {
                unsigned int kbh[4], kbl[4];
                const int off = (g4 * 16 + (lane & 15)) * LDK + c * 16 + (lane >> 4) * 8;
                ldsm_x4(kbh, &sKh[off]);
                ldsm_x4(kbl, &sKl[off]);
                MMA_BF16(sc[2*g4],   qfh[c], kbh[0], kbh[2]);
                MMA_BF16(sc[2*g4],   qfh[c], kbl[0], kbl[2]);
                MMA_BF16(sc[2*g4],   qfl[c], kbh[0], kbh[2]);
                MMA_BF16(sc[2*g4+1], qfh[c], kbh[1], kbh[3]);
                MMA_BF16(sc[2*g4+1], qfh[c], kbl[1], kbl[3]);
                MMA_BF16(sc[2*g4+1], qfl[c], kbh[1], kbh[3]);
            }
        }

        float ml0 = -FLT_MAX, ml1 = -FLT_MAX;
        #pragma unroll
        for (int f = 0; f < 8; f++) {
            const int jc = j0 + f * 8 + t4 * 2;
            bool v00, v01, v10, v11;
            if (MODE == 0) {
                v00 = qv0 && (jc     <= qi0);
                v01 = qv0 && (jc + 1 <= qi0);
                v10 = qv1 && (jc     <= qi1);
                v11 = qv1 && (jc + 1 <= qi1);
            } else {
                bool k0m = sMask[f * 8 + t4 * 2]     != 0;
                bool k1m = sMask[f * 8 + t4 * 2 + 1] != 0;
                v00 = k0m; v01 = k1m; v10 = k0m; v11 = k1m;
            }
            sc[f][0] = v00 ? sc[f][0] * ATT_SCALE : -FLT_MAX;
            sc[f][1] = v01 ? sc[f][1] * ATT_SCALE : -FLT_MAX;
            sc[f][2] = v10 ? sc[f][2] * ATT_SCALE : -FLT_MAX;
            sc[f][3] = v11 ? sc[f][3] * ATT_SCALE : -FLT_MAX;
            ml0 = fmaxf(ml0, fmaxf(sc[f][0], sc[f][1]));
            ml1 = fmaxf(ml1, fmaxf(sc[f][2], sc[f][3]));
        }
        ml0 = fmaxf(ml0, __shfl_xor_sync(0xffffffffu, ml0, 1));
        ml0 = fmaxf(ml0, __shfl_xor_sync(0xffffffffu, ml0, 2));
        ml1 = fmaxf(ml1, __shfl_xor_sync(0xffffffffu, ml1, 1));
        ml1 = fmaxf(ml1, __shfl_xor_sync(0xffffffffu, ml1, 2));

        const float mn0 = fmaxf(M0, ml0), mn1 = fmaxf(M1, ml1);
        const float corr0 = fexp2((M0 - mn0) * L2E);
        const float corr1 = fexp2((M1 - mn1) * L2E);
        L0 *= corr0; L1 *= corr1;
        #pragma unroll
        for (int ni = 0; ni < 4; ni++) {
            O[ni][0] *= corr0; O[ni][1] *= corr0;
            O[ni][2] *= corr1; O[ni][3] *= corr1;
        }

        float ls0 = 0.0f, ls1 = 0.0f;
        unsigned int aH0[8], aH1[8], aL0[8], aL1[8];
        #pragma unroll
        for (int f = 0; f < 8; f++) {
            float p0 = fexp2((sc[f][0] - mn0) * L2E);
            float p1 = fexp2((sc[f][1] - mn0) * L2E);
            float p2 = fexp2((sc[f][2] - mn1) * L2E);
            float p3 = fexp2((sc[f][3] - mn1) * L2E);
            ls0 += p0 + p1; ls1 += p2 + p3;
            unsigned short h0 = bf16_bits(p0), h1 = bf16_bits(p1);
            unsigned short h2 = bf16_bits(p2), h3 = bf16_bits(p3);
            aH0[f] = (unsigned int)h0 | ((unsigned int)h1 << 16);
            aH1[f] = (unsigned int)h2 | ((unsigned int)h3 << 16);
            aL0[f] = pack_bf16x2(p0 - bf16_val(h0), p1 - bf16_val(h1));
            aL1[f] = pack_bf16x2(p2 - bf16_val(h2), p3 - bf16_val(h3));
        }
        ls0 += __shfl_xor_sync(0xffffffffu, ls0, 1);
        ls0 += __shfl_xor_sync(0xffffffffu, ls0, 2);
        ls1 += __shfl_xor_sync(0xffffffffu, ls1, 1);
        ls1 += __shfl_xor_sync(0xffffffffu, ls1, 2);
        L0 += ls0; L1 += ls1;
        M0 = mn0; M1 = mn1;

        #pragma unroll
        for (int kc = 0; kc < 4; kc++) {
            unsigned int pah[4] = { aH0[2*kc], aH1[2*kc], aH0[2*kc+1], aH1[2*kc+1] };
            unsigned int pal[4] = { aL0[2*kc], aL1[2*kc], aL0[2*kc+1], aL1[2*kc+1] };
            #pragma unroll
            for (int ph = 0; ph < 2; ph++) {
                unsigned int vbh[4], vbl[4];
                const int off = (kc * 16 + (lane & 15)) * LDK + ph * 16 + (lane >> 4) * 8;
                ldsm_x4t(vbh, &sVh[off]);
                ldsm_x4t(vbl, &sVl[off]);
                #pragma unroll
                for (int j = 0; j < 2; j++) {
                    const int ni = ph * 2 + j;
                    MMA_BF16(O[ni], pah, vbh[2*j], vbh[2*j+1]);
                    MMA_BF16(O[ni], pah, vbl[2*j], vbl[2*j+1]);
                    MMA_BF16(O[ni], pal, vbh[2*j], vbh[2*j+1]);
                }
            }
        }
    }

    const float inv0 = 1.0f / L0, inv1 = 1.0f / L1;
    const size_t o0 = obase + (size_t)qi0 * DD;
    const size_t o1 = obase + (size_t)qi1 * DD;
    #pragma unroll
    for (int ni = 0; ni < 4; ni++) {
        const int n = ni * 8 + t4 * 2;
        float v00 = O[ni][0] * inv0, v01 = O[ni][1] * inv0;
        float v10 = O[ni][2] * inv1, v11 = O[ni][3] * inv1;
        unsigned short h;
        h = bf16_bits(v00); Oh[o0 + n]     = h; Ol[o0 + n]     = bf16_bits(v00 - bf16_val(h));
        h = bf16_bits(v01); Oh[o0 + n + 1] = h; Ol[o0 + n + 1] = bf16_bits(v01 - bf16_val(h));
        h = bf16_bits(v10); Oh[o1 + n]     = h; Ol[o1 + n]     = bf16_bits(v10 - bf16_val(h));
        h = bf16_bits(v11); Oh[o1 + n + 1] = h; Ol[o1 + n + 1] = bf16_bits(v11 - bf16_val(h));
    }
}

// ---------------- residual + layernorm ---------------------------------------
// MODE 0: bf16 hi/lo split to yh/yl. MODE 1: fp16 single to yh.
template<int MODE>
__global__ __launch_bounds__(128)
void ln_kernel(const float* __restrict__ x, const float* __restrict__ h,
               const float* __restrict__ g, const float* __restrict__ bvec,
               float* __restrict__ y,
               unsigned short* __restrict__ yh, unsigned short* __restrict__ yl) {
    int row = blockIdx.x * 4 + (threadIdx.x >> 5);
    int lane = threadIdx.x & 31;
    const float* xr = x + (size_t)row * DD;
    const float* hr = h + (size_t)row * DD;
    float vals[8];
    float s = 0.0f;
    #pragma unroll
    for (int u = 0; u < 8; u++) {
        int c = lane + u * 32;
        vals[u] = xr[c] + hr[c];
        s += vals[u];
    }
    #pragma unroll
    for (int off = 16; off > 0; off >>= 1) s += __shfl_xor_sync(0xffffffffu, s, off);
    float mean = s * (1.0f / DD);
    float vs = 0.0f;
    #pragma unroll
    for (int u = 0; u < 8; u++) { float d = vals[u] - mean; vs += d * d; }
    #pragma unroll
    for (int off = 16; off > 0; off >>= 1) vs += __shfl_xor_sync(0xffffffffu, vs, off);
    float inv = rsqrtf(vs * (1.0f / DD) + 1e-5f);
    float* yr = y + (size_t)row * DD;
    #pragma unroll
    for (int u = 0; u < 8; u++) {
        int c = lane + u * 32;
        float v = (vals[u] - mean) * inv * g[c] + bvec[c];
        yr[c] = v;
        if (MODE == 0) {
            unsigned short hb = bf16_bits(v);
            yh[(size_t)row * DD + c] = hb;
            yl[(size_t)row * DD + c] = bf16_bits(v - bf16_val(hb));
        } else {
            yh[(size_t)row * DD + c] = fp16_bits(v);
        }
    }
}

// ---------------- launch -----------------------------------------------------
extern "C" void kernel_launch(void* const* d_in, const int* in_sizes, int n_in,
                              void* d_out, int out_size) {
    const float* src_embedded = (const float*)d_in[0];
    const int*   src_mask     = (const int*)d_in[1];
    const void*  tgt_raw      = d_in[2];
    const float* emb   = (const float*)d_in[3];
    const float* pe    = (const float*)d_in[4];
    const float* sa_wq = (const float*)d_in[5];
    const float* sa_wk = (const float*)d_in[6];
    const float* sa_wv = (const float*)d_in[7];
    const float* sa_wo = (const float*)d_in[8];
    const float* sa_bo = (const float*)d_in[9];
    const float* ca_wq = (const float*)d_in[10];
    const float* ca_wk = (const float*)d_in[11];
    const float* ca_wv = (const float*)d_in[12];
    const float* ca_wo = (const float*)d_in[13];
    const float* ca_bo = (const float*)d_in[14];
    const float* ln1_g = (const float*)d_in[15];
    const float* ln1_b = (const float*)d_in[16];
    const float* ln2_g = (const float*)d_in[17];
    const float* ln2_b = (const float*)d_in[18];
    const float* ln3_g = (const float*)d_in[19];
    const float* ln3_b = (const float*)d_in[20];
    const float* fc1_w = (const float*)d_in[21];
    const float* fc1_b = (const float*)d_in[22];
    const float* fc2_w = (const float*)d_in[23];
    const float* fc2_b = (const float*)d_in[24];
    const float* out_w = (const float*)d_in[25];
    const float* out_b = (const float*)d_in[26];

    float *x0, *pr, *x1, *x2, *x3;
    unsigned short *xh, *xl, *eh, *el, *qkvh, *qkvl, *ath, *atl, *ahi, *alo, *bhi, *blo;
    cudaGetSymbolAddress((void**)&x0,   g_x0);
    cudaGetSymbolAddress((void**)&pr,   g_pr);
    cudaGetSymbolAddress((void**)&x1,   g_x1);
    cudaGetSymbolAddress((void**)&x2,   g_x2);
    cudaGetSymbolAddress((void**)&x3,   g_x3);
    cudaGetSymbolAddress((void**)&xh,   g_xh);
    cudaGetSymbolAddress((void**)&xl,   g_xl);
    cudaGetSymbolAddress((void**)&eh,   g_eh);
    cudaGetSymbolAddress((void**)&el,   g_el);
    cudaGetSymbolAddress((void**)&qkvh, g_qkvh);
    cudaGetSymbolAddress((void**)&qkvl, g_qkvl);
    cudaGetSymbolAddress((void**)&ath,  g_ath);
    cudaGetSymbolAddress((void**)&atl,  g_atl);
    cudaGetSymbolAddress((void**)&ahi,  g_ahi);
    cudaGetSymbolAddress((void**)&alo,  g_alo);
    cudaGetSymbolAddress((void**)&bhi,  g_bhi);
    cudaGetSymbolAddress((void**)&blo,  g_blo);

    cudaFuncSetAttribute(mma_gemm<1,1,128>, cudaFuncAttributeMaxDynamicSharedMemorySize, SMEM128);
    cudaFuncSetAttribute(mma_gemm<0,1,64>,  cudaFuncAttributeMaxDynamicSharedMemorySize, SMEM64);
    cudaFuncSetAttribute(mma_gemm<0,0,64>,  cudaFuncAttributeMaxDynamicSharedMemorySize, SMEM64);

    float* outp   = (float*)d_out;
    float* logits = outp;
    float* tgt_out = nullptr;
    long long need = (long long)NROWS * NVOCAB;
    if ((long long)out_size >= need + NROWS) tgt_out = outp + need;

    dim3 gD64(DD / 64, NROWS / 64);
    dim3 gQKV64((3 * DD) / 64, NROWS / 64);
    dim3 gKV64((2 * DD) / 64, NROWS / 64);
    dim3 gF(NDFF / 64, NROWS / 128);
    dim3 gV(NVPAD / 64, NROWS / 128);
    dim3 gAttn(TT / 64, HH, BB);
    const int WB = 256;

    prep_tgt_kernel<<<(NROWS + 127) / 128, 128>>>(tgt_raw, tgt_out);
    embed_kernel<<<(NROWS * DD) / 256, 256>>>(emb, pe);
    conv_w4<<<(DD*DD)/(4*WB), WB>>>(sa_wq, bhi, blo, DD, DD, 3*DD, 0);
    conv_w4<<<(DD*DD)/(4*WB), WB>>>(sa_wk, bhi, blo, DD, DD, 3*DD, DD);
    conv_w4<<<(DD*DD)/(4*WB), WB>>>(sa_wv, bhi, blo, DD, DD, 3*DD, 2*DD);
    mma_gemm<0,1,64><<<gQKV64, 128, SMEM64>>>(xh, xl, bhi, blo, nullptr, nullptr,
                                              qkvh, qkvl, NROWS, 3*DD, DD, 3*DD, 3*DD);
    attn_mma<0><<<gAttn, 128>>>(qkvh, qkvl, qkvh + DD, qkvl + DD,
                                qkvh + 2*DD, qkvl + 2*DD, ath, atl, nullptr);
    conv_w4<<<(DD*DD)/(4*WB), WB>>>(sa_wo, bhi, blo, DD, DD, DD, 0);
    mma_gemm<0,0,64><<<gD64, 128, SMEM64>>>(ath, atl, bhi, blo, sa_bo, pr,
                                            nullptr, nullptr, NROWS, DD, DD, DD, DD);
    ln_kernel<0><<<NROWS / 4, 128>>>(x0, pr, ln1_g, ln1_b, x1, xh, xl);

    // ---- cross-attention block ----
    encmask_kernel<<<(NROWS * DD) / 256, 256>>>(src_embedded, src_mask);
    conv_w4<<<(DD*DD)/(4*WB), WB>>>(ca_wq, bhi, blo, DD, DD, DD, 0);
    mma_gemm<0,1,64><<<gD64, 128, SMEM64>>>(xh, xl, bhi, blo, nullptr, nullptr,
                                            qkvh, qkvl, NROWS, DD, DD, DD, 3*DD);
    conv_w4<<<(DD*DD)/(4*WB), WB>>>(ca_wk, bhi, blo, DD, DD, 2*DD, 0);
    conv_w4<<<(DD*DD)/(4*WB), WB>>>(ca_wv, bhi, blo, DD, DD, 2*DD, DD);
    mma_gemm<0,1,64><<<gKV64, 128, SMEM64>>>(eh, el, bhi, blo, nullptr, nullptr,
                                             qkvh + DD, qkvl + DD, NROWS, 2*DD, DD, 2*DD, 3*DD);
    attn_mma<1><<<gAttn, 128>>>(qkvh, qkvl, qkvh + DD, qkvl + DD,
                                qkvh + 2*DD, qkvl + 2*DD, ath, atl, src_mask);
    conv_w4<<<(DD*DD)/(4*WB), WB>>>(ca_wo, bhi, blo, DD, DD, DD, 0);
    mma_gemm<0,0,64><<<gD64, 128, SMEM64>>>(ath, atl, bhi, blo, ca_bo, pr,
                                            nullptr, nullptr, NROWS, DD, DD, DD, DD);
    ln_kernel<0><<<NROWS / 4, 128>>>(x1, pr, ln2_g, ln2_b, x2, xh, xl);

    // ---- FFN ----
    conv_w4<<<(DD*NDFF)/(4*WB), WB>>>(fc1_w, bhi, blo, DD, NDFF, NDFF, 0);
    mma_gemm<1,1,128><<<gF, 256, SMEM128>>>(xh, xl, bhi, blo, fc1_b, nullptr,
                                            ahi, alo, NROWS, NDFF, DD, NDFF, NDFF);
    conv_w4<<<(NDFF*DD)/(4*WB), WB>>>(fc2_w, bhi, blo, NDFF, DD, DD, 0);
    mma_gemm<0,0,64><<<gD64, 128, SMEM64>>>(ahi, alo, bhi, blo, fc2_b, pr,
                                            nullptr, nullptr, NROWS, DD, NDFF, DD, DD);
    // LN3 emits fp16 activations for the vocab GEMM
    ln_kernel<1><<<NROWS / 4, 128>>>(x2, pr, ln3_g, ln3_b, x3, xh, nullptr);

    // ---- vocab projection: single-pass fp16 tensor-core GEMM ----
    conv_pad_h4<<<(DD*NVPAD)/(4*WB), WB>>>(out_w, bhi, DD, NVOCAB, NVPAD);
    mma_gemm_h<<<gV, 256, SMEM_H>>>(xh, bhi, out_b, logits,
                                    NROWS, NVOCAB, DD, NVPAD, NVOCAB);
}

// round 15
// speedup vs baseline: 1.5848x; 1.1004x over previous
#include <cuda_runtime.h>
#include <cuda_bf16.h>
#include <cuda_fp16.h>
#include <cstdint>
#include <cstdio>
#include <math.h>
#include <float.h>

#define BB 2
#define SS 2048
#define TT 2048
#define NVOCAB 25426
#define NVPAD 25472
#define DD 256
#define HH 8
#define DHH 32
#define NDFF 2048
#define NROWS (BB*TT)
#define T0LEN (TT-1)

// ---------------- scratch ----------------------------------------------------
static __device__ float g_x0 [NROWS*DD];
static __device__ float g_pr [NROWS*DD];
static __device__ float g_x1 [NROWS*DD];
static __device__ float g_x2 [NROWS*DD];
static __device__ float g_x3 [NROWS*DD];
static __device__ int   g_tgt[NROWS];
// bf16 hi/lo buffers (xh doubles as fp16 buffer after LN2/LN3)
static __device__ unsigned short g_xh [NROWS*DD],   g_xl [NROWS*DD];
static __device__ unsigned short g_eh [NROWS*DD],   g_el [NROWS*DD];
static __device__ unsigned short g_qkvh[NROWS*3*DD], g_qkvl[NROWS*3*DD];
static __device__ unsigned short g_ath[NROWS*DD];   // fp16 attention out
static __device__ unsigned short g_ahi[NROWS*NDFF]; // fp16 ff1
static __device__ unsigned short g_bhi[DD*NVPAD],   g_blo[DD*NVPAD];

// ---------------- helpers ----------------------------------------------------
__device__ __forceinline__ unsigned short bf16_bits(float v) {
    return (unsigned short)__bfloat16_as_ushort(__float2bfloat16(v));
}
__device__ __forceinline__ float bf16_val(unsigned short u) {
    return __bfloat162float(__ushort_as_bfloat16(u));
}
__device__ __forceinline__ unsigned short fp16_bits(float v) {
    return (unsigned short)__half_as_ushort(__float2half_rn(v));
}
__device__ __forceinline__ unsigned int pack_bf16x2(float lo, float hi) {
    unsigned int r;
    asm("cvt.rn.bf16x2.f32 %0, %1, %2;" : "=r"(r) : "f"(hi), "f"(lo));
    return r;
}
__device__ __forceinline__ float fexp2(float t) {
    t = fmaxf(t, -126.0f);
    float z  = t + 12582912.0f;
    float fi = z - 12582912.0f;
    float f  = t - fi;
    int   ii = __float_as_int(z) - 0x4B400000;
    float p = 1.54035304e-4f;
    p = fmaf(p, f, 1.33335581e-3f);
    p = fmaf(p, f, 9.61812910e-3f);
    p = fmaf(p, f, 5.55041087e-2f);
    p = fmaf(p, f, 2.40226507e-1f);
    p = fmaf(p, f, 6.93147181e-1f);
    p = fmaf(p, f, 1.0f);
    return __int_as_float(__float_as_int(p) + (ii << 23));
}
#define L2E 1.4426950408889634f

// ---------------- prep kernels -----------------------------------------------
__global__ void prep_tgt_kernel(const void* __restrict__ tgt_raw,
                                float* __restrict__ tgt_out) {
    __shared__ int s_odd;
    if (threadIdx.x == 0) s_odd = 0;
    __syncthreads();
    const int* raw = (const int*)tgt_raw;
    int local = 0;
    for (int i = threadIdx.x; i < BB * T0LEN; i += blockDim.x)
        if ((i & 1) && raw[i] != 0) local = 1;
    if (local) atomicOr(&s_odd, 1);
    __syncthreads();
    int is64 = s_odd ? 0 : 1;

    int idx = blockIdx.x * blockDim.x + threadIdx.x;
    if (idx >= NROWS) return;
    int b = idx / TT, t = idx % TT;
    int id;
    if (t == 0) id = NVOCAB;
    else {
        size_t src = (size_t)b * T0LEN + (t - 1);
        if (is64) id = (int)((const long long*)tgt_raw)[src];
        else      id = ((const int*)tgt_raw)[src];
    }
    if (id < 0) id = 0;
    if (id > NVOCAB) id = NVOCAB;
    g_tgt[idx] = id;
    if (tgt_out) tgt_out[idx] = (t == 0) ? 0.0f : (float)id;
}

__global__ void embed_kernel(const float* __restrict__ emb,
                             const float* __restrict__ pe) {
    int idx = blockIdx.x * blockDim.x + threadIdx.x;
    if (idx >= NROWS * DD) return;
    int row = idx >> 8, d = idx & 255, t = row & (TT - 1);
    int id = g_tgt[row];
    float v = 2.0f * emb[(size_t)id * DD + d] + pe[(size_t)t * DD + d];
    g_x0[idx] = v;
    unsigned short h = bf16_bits(v);
    g_xh[idx] = h;
    g_xl[idx] = bf16_bits(v - bf16_val(h));
}

__global__ void encmask_kernel(const float* __restrict__ src,
                               const int* __restrict__ mask) {
    int idx = blockIdx.x * blockDim.x + threadIdx.x;
    if (idx >= NROWS * DD) return;
    float v = mask[idx >> 8] ? src[idx] : 0.0f;
    unsigned short h = bf16_bits(v);
    g_eh[idx] = h;
    g_el[idx] = bf16_bits(v - bf16_val(h));
}

__global__ void conv_w4(const float* __restrict__ x,
                        unsigned short* __restrict__ hi,
                        unsigned short* __restrict__ lo,
                        int K, int N, int ldb, int col0) {
    int i = (blockIdx.x * blockDim.x + threadIdx.x) * 4;
    if (i >= K * N) return;
    int r = i / N, c = i % N;
    float4 v = *reinterpret_cast<const float4*>(x + (size_t)r * N + c);
    ushort4 h, l;
    h.x = bf16_bits(v.x); l.x = bf16_bits(v.x - bf16_val(h.x));
    h.y = bf16_bits(v.y); l.y = bf16_bits(v.y - bf16_val(h.y));
    h.z = bf16_bits(v.z); l.z = bf16_bits(v.z - bf16_val(h.z));
    h.w = bf16_bits(v.w); l.w = bf16_bits(v.w - bf16_val(h.w));
    size_t dst = (size_t)r * ldb + col0 + c;
    *reinterpret_cast<ushort4*>(hi + dst) = h;
    *reinterpret_cast<ushort4*>(lo + dst) = l;
}

// fp16 pad convert (single array, zero pad to ldb)
__global__ void conv_pad_h4(const float* __restrict__ x,
                            unsigned short* __restrict__ hi,
                            int K, int N, int ldb) {
    int i = (blockIdx.x * blockDim.x + threadIdx.x) * 4;
    if (i >= K * ldb) return;
    int r = i / ldb, c = i % ldb;
    ushort4 h;
    float vv[4];
    #pragma unroll
    for (int j = 0; j < 4; j++) {
        int cc = c + j;
        vv[j] = (cc < N) ? x[(size_t)r * N + cc] : 0.0f;
    }
    h.x = fp16_bits(vv[0]); h.y = fp16_bits(vv[1]);
    h.z = fp16_bits(vv[2]); h.w = fp16_bits(vv[3]);
    *reinterpret_cast<ushort4*>(hi + i) = h;
}

// ---------------- MMA primitives ---------------------------------------------
#define MMA_BF16(ac, a, b0, b1)                                              \
    asm volatile("mma.sync.aligned.m16n8k16.row.col.f32.bf16.bf16.f32 "      \
                 "{%0,%1,%2,%3},{%4,%5,%6,%7},{%8,%9},{%0,%1,%2,%3};"        \
                 : "+f"(ac[0]), "+f"(ac[1]), "+f"(ac[2]), "+f"(ac[3])        \
                 : "r"(a[0]), "r"(a[1]), "r"(a[2]), "r"(a[3]),               \
                   "r"(b0), "r"(b1))

#define MMA_F16(ac, a, b0, b1)                                               \
    asm volatile("mma.sync.aligned.m16n8k16.row.col.f32.f16.f16.f32 "        \
                 "{%0,%1,%2,%3},{%4,%5,%6,%7},{%8,%9},{%0,%1,%2,%3};"        \
                 : "+f"(ac[0]), "+f"(ac[1]), "+f"(ac[2]), "+f"(ac[3])        \
                 : "r"(a[0]), "r"(a[1]), "r"(a[2]), "r"(a[3]),               \
                   "r"(b0), "r"(b1))

__device__ __forceinline__ void ldsm_x4(unsigned int* r, const unsigned short* p) {
    unsigned int sa = (unsigned int)__cvta_generic_to_shared(p);
    asm volatile("ldmatrix.sync.aligned.m8n8.x4.shared.b16 {%0,%1,%2,%3},[%4];"
                 : "=r"(r[0]), "=r"(r[1]), "=r"(r[2]), "=r"(r[3]) : "r"(sa));
}
__device__ __forceinline__ void ldsm_x4t(unsigned int* r, const unsigned short* p) {
    unsigned int sa = (unsigned int)__cvta_generic_to_shared(p);
    asm volatile("ldmatrix.sync.aligned.m8n8.x4.trans.shared.b16 {%0,%1,%2,%3},[%4];"
                 : "=r"(r[0]), "=r"(r[1]), "=r"(r[2]), "=r"(r[3]) : "r"(sa));
}
__device__ __forceinline__ void cp16(unsigned short* sdst, const unsigned short* gsrc) {
    unsigned int d = (unsigned int)__cvta_generic_to_shared(sdst);
    asm volatile("cp.async.cg.shared.global [%0], [%1], 16;" :: "r"(d), "l"(gsrc));
}
#define CP_COMMIT() asm volatile("cp.async.commit_group;" ::: "memory")
#define CP_WAIT0()  asm volatile("cp.async.wait_group 0;" ::: "memory")
#define CP_WAIT1()  asm volatile("cp.async.wait_group 1;" ::: "memory")

// ---------------- tensor-core GEMM (bf16 split, BM template) -----------------
#define LDA_S 40
#define LDB_S 72

template<int ACT, int OUTM, int BM>
__global__ __launch_bounds__(BM * 2)
void mma_gemm(const unsigned short* __restrict__ Ahi,
              const unsigned short* __restrict__ Alo,
              const unsigned short* __restrict__ Bhi,
              const unsigned short* __restrict__ Blo,
              const float* __restrict__ bias, float* __restrict__ C,
              unsigned short* __restrict__ Ch, unsigned short* __restrict__ Cl,
              int M, int N, int K, int ldb, int ldc) {
    constexpr int A_SZ = BM * LDA_S;
    constexpr int STG  = 2 * A_SZ + 2 * 32 * LDB_S;
    constexpr int AH = 0, AL = A_SZ, BH = 2 * A_SZ, BL = 2 * A_SZ + 32 * LDB_S;
    extern __shared__ __align__(16) unsigned short smem_u[];

    const int tid = threadIdx.x, lane = tid & 31, warp = tid >> 5;
    const int wm = warp >> 1, wn = warp & 1;
    const int m0 = blockIdx.y * BM, n0 = blockIdx.x * 64;
    const int ar = tid >> 1, ac = (tid & 1) * 16;

    float acc[2][4][4] = {};

    auto issue_tile = [&](int k0, int st) {
        unsigned short* base = smem_u + st * STG;
        const unsigned short* gAh = Ahi + (size_t)(m0 + ar) * K + k0 + ac;
        const unsigned short* gAl = Alo + (size_t)(m0 + ar) * K + k0 + ac;
        cp16(base + AH + ar * LDA_S + ac,     gAh);
        cp16(base + AH + ar * LDA_S + ac + 8, gAh + 8);
        cp16(base + AL + ar * LDA_S + ac,     gAl);
        cp16(base + AL + ar * LDA_S + ac + 8, gAl + 8);
        if (BM == 128) {
            const int br = tid >> 3, bc = (tid & 7) * 8;
            const size_t gb = (size_t)(k0 + br) * ldb + n0 + bc;
            cp16(base + BH + br * LDB_S + bc, Bhi + gb);
            cp16(base + BL + br * LDB_S + bc, Blo + gb);
        } else {
            const int br = tid >> 2, bc = (tid & 3) * 16;
            const size_t gb = (size_t)(k0 + br) * ldb + n0 + bc;
            cp16(base + BH + br * LDB_S + bc,     Bhi + gb);
            cp16(base + BH + br * LDB_S + bc + 8, Bhi + gb + 8);
            cp16(base + BL + br * LDB_S + bc,     Blo + gb);
            cp16(base + BL + br * LDB_S + bc + 8, Blo + gb + 8);
        }
    };

    issue_tile(0, 0);
    CP_COMMIT();

    int buf = 0;
    for (int k0 = 0; k0 < K; k0 += 32) {
        if (k0 + 32 < K) { issue_tile(k0 + 32, buf ^ 1); CP_COMMIT(); CP_WAIT1(); }
        else             { CP_WAIT0(); }
        __syncthreads();

        const unsigned short* sAh = smem_u + buf * STG + AH;
        const unsigned short* sAl = smem_u + buf * STG + AL;
        const unsigned short* sBh = smem_u + buf * STG + BH;
        const unsigned short* sBl = smem_u + buf * STG + BL;

        #pragma unroll
        for (int ks = 0; ks < 32; ks += 16) {
            unsigned int ah[2][4], al[2][4];
            #pragma unroll
            for (int mi = 0; mi < 2; mi++) {
                const int off = (wm * 32 + mi * 16 + (lane & 15)) * LDA_S
                                + ks + (lane >> 4) * 8;
                ldsm_x4(ah[mi], &sAh[off]);
                ldsm_x4(al[mi], &sAl[off]);
            }
            unsigned int bh[2][4], bl[2][4];
            #pragma unroll
            for (int p = 0; p < 2; p++) {
                const int off = (ks + (lane & 15)) * LDB_S
                                + wn * 32 + p * 16 + (lane >> 4) * 8;
                ldsm_x4t(bh[p], &sBh[off]);
                ldsm_x4t(bl[p], &sBl[off]);
            }
            #pragma unroll
            for (int mi = 0; mi < 2; mi++) {
                #pragma unroll
                for (int ni = 0; ni < 4; ni++) {
                    unsigned int bh0 = bh[ni >> 1][(ni & 1) * 2];
                    unsigned int bh1 = bh[ni >> 1][(ni & 1) * 2 + 1];
                    unsigned int bl0 = bl[ni >> 1][(ni & 1) * 2];
                    unsigned int bl1 = bl[ni >> 1][(ni & 1) * 2 + 1];
                    MMA_BF16(acc[mi][ni], ah[mi], bh0, bh1);
                    MMA_BF16(acc[mi][ni], ah[mi], bl0, bl1);
                    MMA_BF16(acc[mi][ni], al[mi], bh0, bh1);
                }
            }
        }
        __syncthreads();
        buf ^= 1;
    }

    const int grp = lane >> 2, t4 = lane & 3;
    #pragma unroll
    for (int mi = 0; mi < 2; mi++) {
        #pragma unroll
        for (int ni = 0; ni < 4; ni++) {
            int row = m0 + wm * 32 + mi * 16 + grp;
            int col = n0 + wn * 32 + ni * 8 + t4 * 2;
            #pragma unroll
            for (int hv = 0; hv < 2; hv++) {
                int r = row + hv * 8;
                #pragma unroll
                for (int cc = 0; cc < 2; cc++) {
                    int n = col + cc;
                    if (n >= N) continue;
                    float v = acc[mi][ni][hv * 2 + cc] + (bias ? bias[n] : 0.0f);
                    if (ACT == 1) v = 0.5f * v * (1.0f + erff(v * 0.70710678118654752f));
                    if (OUTM == 0) {
                        C[(size_t)r * ldc + n] = v;
                    } else {
                        unsigned short h = bf16_bits(v);
                        Ch[(size_t)r * ldc + n] = h;
                        Cl[(size_t)r * ldc + n] = bf16_bits(v - bf16_val(h));
                    }
                }
            }
        }
    }
}

#define STG128   (2*128*LDA_S + 2*32*LDB_S)
#define SMEM128  (2 * STG128 * 2)
#define STG64    (2*64*LDA_S + 2*32*LDB_S)
#define SMEM64   (2 * STG64 * 2)

// ---------------- fp16 single-pass GEMM: BM x 64 x BK32 ----------------------
// ACT: 0 none, 1 GELU. OUTH: 0 fp32 C, 1 fp16 Ch.
template<int ACT, int OUTH, int BM>
__global__ __launch_bounds__(BM * 2)
void mma_gemm_h(const unsigned short* __restrict__ Ah,
                const unsigned short* __restrict__ Bh,
                const float* __restrict__ bias, float* __restrict__ C,
                unsigned short* __restrict__ Ch,
                int M, int N, int K, int ldb, int ldc) {
    constexpr int A_SZ = BM * LDA_S;
    constexpr int STG  = A_SZ + 32 * LDB_S;
    constexpr int AH = 0, BH = A_SZ;
    extern __shared__ __align__(16) unsigned short smem_u[];

    const int tid = threadIdx.x, lane = tid & 31, warp = tid >> 5;
    const int wm = warp >> 1, wn = warp & 1;
    const int m0 = blockIdx.y * BM, n0 = blockIdx.x * 64;
    const int ar = tid >> 1, ac = (tid & 1) * 16;

    float acc[2][4][4] = {};

    auto issue_tile = [&](int k0, int st) {
        unsigned short* base = smem_u + st * STG;
        const unsigned short* gA = Ah + (size_t)(m0 + ar) * K + k0 + ac;
        cp16(base + AH + ar * LDA_S + ac,     gA);
        cp16(base + AH + ar * LDA_S + ac + 8, gA + 8);
        if (BM == 128) {
            const int br = tid >> 3, bc = (tid & 7) * 8;
            const size_t gb = (size_t)(k0 + br) * ldb + n0 + bc;
            cp16(base + BH + br * LDB_S + bc, Bh + gb);
        } else {
            const int br = tid >> 2, bc = (tid & 3) * 16;
            const size_t gb = (size_t)(k0 + br) * ldb + n0 + bc;
            cp16(base + BH + br * LDB_S + bc,     Bh + gb);
            cp16(base + BH + br * LDB_S + bc + 8, Bh + gb + 8);
        }
    };

    issue_tile(0, 0);
    CP_COMMIT();

    int buf = 0;
    for (int k0 = 0; k0 < K; k0 += 32) {
        if (k0 + 32 < K) { issue_tile(k0 + 32, buf ^ 1); CP_COMMIT(); CP_WAIT1(); }
        else             { CP_WAIT0(); }
        __syncthreads();

        const unsigned short* sA = smem_u + buf * STG + AH;
        const unsigned short* sB = smem_u + buf * STG + BH;

        #pragma unroll
        for (int ks = 0; ks < 32; ks += 16) {
            unsigned int a[2][4];
            #pragma unroll
            for (int mi = 0; mi < 2; mi++) {
                const int off = (wm * 32 + mi * 16 + (lane & 15)) * LDA_S
                                + ks + (lane >> 4) * 8;
                ldsm_x4(a[mi], &sA[off]);
            }
            unsigned int b[2][4];
            #pragma unroll
            for (int p = 0; p < 2; p++) {
                const int off = (ks + (lane & 15)) * LDB_S
                                + wn * 32 + p * 16 + (lane >> 4) * 8;
                ldsm_x4t(b[p], &sB[off]);
            }
            #pragma unroll
            for (int mi = 0; mi < 2; mi++) {
                #pragma unroll
                for (int ni = 0; ni < 4; ni++) {
                    unsigned int b0 = b[ni >> 1][(ni & 1) * 2];
                    unsigned int b1 = b[ni >> 1][(ni & 1) * 2 + 1];
                    MMA_F16(acc[mi][ni], a[mi], b0, b1);
                }
            }
        }
        __syncthreads();
        buf ^= 1;
    }

    const int grp = lane >> 2, t4 = lane & 3;
    #pragma unroll
    for (int mi = 0; mi < 2; mi++) {
        #pragma unroll
        for (int ni = 0; ni < 4; ni++) {
            int row = m0 + wm * 32 + mi * 16 + grp;
            int col = n0 + wn * 32 + ni * 8 + t4 * 2;
            #pragma unroll
            for (int hv = 0; hv < 2; hv++) {
                int r = row + hv * 8;
                #pragma unroll
                for (int cc = 0; cc < 2; cc++) {
                    int n = col + cc;
                    if (n >= N) continue;
                    float v = acc[mi][ni][hv * 2 + cc] + (bias ? bias[n] : 0.0f);
                    if (ACT == 1) v = 0.5f * v * (1.0f + erff(v * 0.70710678118654752f));
                    if (OUTH == 0) C[(size_t)r * ldc + n] = v;
                    else           Ch[(size_t)r * ldc + n] = fp16_bits(v);
                }
            }
        }
    }
}

#define STG_H128  (128*LDA_S + 32*LDB_S)
#define SMEM_H128 (2 * STG_H128 * 2)       // 29696 B
#define STG_H64   (64*LDA_S + 32*LDB_S)
#define SMEM_H64  (2 * STG_H64 * 2)        // 19456 B

// ---------------- tensor-core flash attention (fp16 output) ------------------
#define LDK 40
#define ATT_SCALE 0.17677669529663687f
#define QKV_LD (3*DD)

template<int MODE>
__global__ __launch_bounds__(128)
void attn_mma(const unsigned short* __restrict__ Qh, const unsigned short* __restrict__ Ql,
              const unsigned short* __restrict__ Kh, const unsigned short* __restrict__ Kl,
              const unsigned short* __restrict__ Vh, const unsigned short* __restrict__ Vl,
              unsigned short* __restrict__ Oh,
              const int* __restrict__ aux) {
    const int b = blockIdx.z, h = blockIdx.y, blk = blockIdx.x;
    const int tid = threadIdx.x, lane = tid & 31, w = tid >> 5;
    const int grp = lane >> 2, t4 = lane & 3;
    const size_t rowbase = (size_t)b * TT * QKV_LD + h * DHH;
    const size_t obase   = (size_t)b * TT * DD + h * DHH;

    __shared__ __align__(16) unsigned short sQh[64*LDK], sQl[64*LDK];
    __shared__ __align__(16) unsigned short sKh[64*LDK], sKl[64*LDK];
    __shared__ __align__(16) unsigned short sVh[64*LDK], sVl[64*LDK];
    __shared__ int sMask[64];

    {
        int r = tid >> 1, cs = (tid & 1) * 16;
        size_t g = rowbase + (size_t)(blk * 64 + r) * QKV_LD + cs;
        *(uint4*)&sQh[r*LDK+cs]   = *(const uint4*)(Qh + g);
        *(uint4*)&sQh[r*LDK+cs+8] = *(const uint4*)(Qh + g + 8);
        *(uint4*)&sQl[r*LDK+cs]   = *(const uint4*)(Ql + g);
        *(uint4*)&sQl[r*LDK+cs+8] = *(const uint4*)(Ql + g + 8);
    }

    const int qi0 = blk * 64 + w * 16 + grp;
    const int qi1 = qi0 + 8;
    bool qv0 = true, qv1 = true;
    int pred = 0;
    if (MODE == 0) {
        qv0 = (g_tgt[b * TT + qi0] != 0);
        qv1 = (g_tgt[b * TT + qi1] != 0);
        pred = (tid < 64) && (g_tgt[b * TT + blk * 64 + tid] == 0);
    }
    int ext = __syncthreads_or(pred);

    unsigned int qfh[2][4], qfl[2][4];
    #pragma unroll
    for (int c = 0; c < 2; c++) {
        const int off = (w * 16 + (lane & 15)) * LDK + c * 16 + (lane >> 4) * 8;
        ldsm_x4(qfh[c], &sQh[off]);
        ldsm_x4(qfl[c], &sQl[off]);
    }

    const int nT = (MODE == 0) ? (ext ? TT / 64 : (blk + 1)) : SS / 64;

    float M0 = -FLT_MAX, M1 = -FLT_MAX, L0 = 0.0f, L1 = 0.0f;
    float O[4][4] = {};

    for (int tile = 0; tile < nT; tile++) {
        const int j0 = tile * 64;
        __syncthreads();
        {
            int r = tid >> 1, cs = (tid & 1) * 16;
            size_t g = rowbase + (size_t)(j0 + r) * QKV_LD + cs;
            *(uint4*)&sKh[r*LDK+cs]   = *(const uint4*)(Kh + g);
            *(uint4*)&sKh[r*LDK+cs+8] = *(const uint4*)(Kh + g + 8);
            *(uint4*)&sKl[r*LDK+cs]   = *(const uint4*)(Kl + g);
            *(uint4*)&sKl[r*LDK+cs+8] = *(const uint4*)(Kl + g + 8);
            *(uint4*)&sVh[r*LDK+cs]   = *(const uint4*)(Vh + g);
            *(uint4*)&sVh[r*LDK+cs+8] = *(const uint4*)(Vh + g + 8);
            *(uint4*)&sVl[r*LDK+cs]   = *(const uint4*)(Vl + g);
            *(uint4*)&sVl[r*LDK+cs+8] = *(const uint4*)(Vl + g + 8);
            if (MODE == 1 && tid < 64) sMask[tid] = aux[b * SS + j0 + tid];
        }
        __syncthreads();

        float sc[8][4] = {};
        #pragma unroll
        for (int c = 0; c < 2; c++) {
            #pragma unroll
            for (int g4 = 0; g4 < 4; g4++) {
                unsigned int kbh[4], kbl[4];
                const int off = (g4 * 16 + (lane & 15)) * LDK + c * 16 + (lane >> 4) * 8;
                ldsm_x4(kbh, &sKh[off]);
                ldsm_x4(kbl, &sKl[off]);
                MMA_BF16(sc[2*g4],   qfh[c], kbh[0], kbh[2]);
                MMA_BF16(sc[2*g4],   qfh[c], kbl[0], kbl[2]);
                MMA_BF16(sc[2*g4],   qfl[c], kbh[0], kbh[2]);
                MMA_BF16(sc[2*g4+1], qfh[c], kbh[1], kbh[3]);
                MMA_BF16(sc[2*g4+1], qfh[c], kbl[1], kbl[3]);
                MMA_BF16(sc[2*g4+1], qfl[c], kbh[1], kbh[3]);
            }
        }

        float ml0 = -FLT_MAX, ml1 = -FLT_MAX;
        #pragma unroll
        for (int f = 0; f < 8; f++) {
            const int jc = j0 + f * 8 + t4 * 2;
            bool v00, v01, v10, v11;
            if (MODE == 0) {
                v00 = qv0 && (jc     <= qi0);
                v01 = qv0 && (jc + 1 <= qi0);
                v10 = qv1 && (jc     <= qi1);
                v11 = qv1 && (jc + 1 <= qi1);
            } else {
                bool k0m = sMask[f * 8 + t4 * 2]     != 0;
                bool k1m = sMask[f * 8 + t4 * 2 + 1] != 0;
                v00 = k0m; v01 = k1m; v10 = k0m; v11 = k1m;
            }
            sc[f][0] = v00 ? sc[f][0] * ATT_SCALE : -FLT_MAX;
            sc[f][1] = v01 ? sc[f][1] * ATT_SCALE : -FLT_MAX;
            sc[f][2] = v10 ? sc[f][2] * ATT_SCALE : -FLT_MAX;
            sc[f][3] = v11 ? sc[f][3] * ATT_SCALE : -FLT_MAX;
            ml0 = fmaxf(ml0, fmaxf(sc[f][0], sc[f][1]));
            ml1 = fmaxf(ml1, fmaxf(sc[f][2], sc[f][3]));
        }
        ml0 = fmaxf(ml0, __shfl_xor_sync(0xffffffffu, ml0, 1));
        ml0 = fmaxf(ml0, __shfl_xor_sync(0xffffffffu, ml0, 2));
        ml1 = fmaxf(ml1, __shfl_xor_sync(0xffffffffu, ml1, 1));
        ml1 = fmaxf(ml1, __shfl_xor_sync(0xffffffffu, ml1, 2));

        const float mn0 = fmaxf(M0, ml0), mn1 = fmaxf(M1, ml1);
        const float corr0 = fexp2((M0 - mn0) * L2E);
        const float corr1 = fexp2((M1 - mn1) * L2E);
        L0 *= corr0; L1 *= corr1;
        #pragma unroll
        for (int ni = 0; ni < 4; ni++) {
            O[ni][0] *= corr0; O[ni][1] *= corr0;
            O[ni][2] *= corr1; O[ni][3] *= corr1;
        }

        float ls0 = 0.0f, ls1 = 0.0f;
        unsigned int aH0[8], aH1[8], aL0[8], aL1[8];
        #pragma unroll
        for (int f = 0; f < 8; f++) {
            float p0 = fexp2((sc[f][0] - mn0) * L2E);
            float p1 = fexp2((sc[f][1] - mn0) * L2E);
            float p2 = fexp2((sc[f][2] - mn1) * L2E);
            float p3 = fexp2((sc[f][3] - mn1) * L2E);
            ls0 += p0 + p1; ls1 += p2 + p3;
            unsigned short h0 = bf16_bits(p0), h1 = bf16_bits(p1);
            unsigned short h2 = bf16_bits(p2), h3 = bf16_bits(p3);
            aH0[f] = (unsigned int)h0 | ((unsigned int)h1 << 16);
            aH1[f] = (unsigned int)h2 | ((unsigned int)h3 << 16);
            aL0[f] = pack_bf16x2(p0 - bf16_val(h0), p1 - bf16_val(h1));
            aL1[f] = pack_bf16x2(p2 - bf16_val(h2), p3 - bf16_val(h3));
        }
        ls0 += __shfl_xor_sync(0xffffffffu, ls0, 1);
        ls0 += __shfl_xor_sync(0xffffffffu, ls0, 2);
        ls1 += __shfl_xor_sync(0xffffffffu, ls1, 1);
        ls1 += __shfl_xor_sync(0xffffffffu, ls1, 2);
        L0 += ls0; L1 += ls1;
        M0 = mn0; M1 = mn1;

        #pragma unroll
        for (int kc = 0; kc < 4; kc++) {
            unsigned int pah[4] = { aH0[2*kc], aH1[2*kc], aH0[2*kc+1], aH1[2*kc+1] };
            unsigned int pal[4] = { aL0[2*kc], aL1[2*kc], aL0[2*kc+1], aL1[2*kc+1] };
            #pragma unroll
            for (int ph = 0; ph < 2; ph++) {
                unsigned int vbh[4], vbl[4];
                const int off = (kc * 16 + (lane & 15)) * LDK + ph * 16 + (lane >> 4) * 8;
                ldsm_x4t(vbh, &sVh[off]);
                ldsm_x4t(vbl, &sVl[off]);
                #pragma unroll
                for (int j = 0; j < 2; j++) {
                    const int ni = ph * 2 + j;
                    MMA_BF16(O[ni], pah, vbh[2*j], vbh[2*j+1]);
                    MMA_BF16(O[ni], pah, vbl[2*j], vbl[2*j+1]);
                    MMA_BF16(O[ni], pal, vbh[2*j], vbh[2*j+1]);
                }
            }
        }
    }

    const float inv0 = 1.0f / L0, inv1 = 1.0f / L1;
    const size_t o0 = obase + (size_t)qi0 * DD;
    const size_t o1 = obase + (size_t)qi1 * DD;
    #pragma unroll
    for (int ni = 0; ni < 4; ni++) {
        const int n = ni * 8 + t4 * 2;
        Oh[o0 + n]     = fp16_bits(O[ni][0] * inv0);
        Oh[o0 + n + 1] = fp16_bits(O[ni][1] * inv0);
        Oh[o1 + n]     = fp16_bits(O[ni][2] * inv1);
        Oh[o1 + n + 1] = fp16_bits(O[ni][3] * inv1);
    }
}

// ---------------- residual + layernorm ---------------------------------------
// MODE 0: bf16 hi/lo split to yh/yl. MODE 1: fp16 single to yh.
template<int MODE>
__global__ __launch_bounds__(128)
void ln_kernel(const float* __restrict__ x, const float* __restrict__ h,
               const float* __restrict__ g, const float* __restrict__ bvec,
               float* __restrict__ y,
               unsigned short* __restrict__ yh, unsigned short* __restrict__ yl) {
    int row = blockIdx.x * 4 + (threadIdx.x >> 5);
    int lane = threadIdx.x & 31;
    const float* xr = x + (size_t)row * DD;
    const float* hr = h + (size_t)row * DD;
    float vals[8];
    float s = 0.0f;
    #pragma unroll
    for (int u = 0; u < 8; u++) {
        int c = lane + u * 32;
        vals[u] = xr[c] + hr[c];
        s += vals[u];
    }
    #pragma unroll
    for (int off = 16; off > 0; off >>= 1) s += __shfl_xor_sync(0xffffffffu, s, off);
    float mean = s * (1.0f / DD);
    float vs = 0.0f;
    #pragma unroll
    for (int u = 0; u < 8; u++) { float d = vals[u] - mean; vs += d * d; }
    #pragma unroll
    for (int off = 16; off > 0; off >>= 1) vs += __shfl_xor_sync(0xffffffffu, vs, off);
    float inv = rsqrtf(vs * (1.0f / DD) + 1e-5f);
    float* yr = y + (size_t)row * DD;
    #pragma unroll
    for (int u = 0; u < 8; u++) {
        int c = lane + u * 32;
        float v = (vals[u] - mean) * inv * g[c] + bvec[c];
        yr[c] = v;
        if (MODE == 0) {
            unsigned short hb = bf16_bits(v);
            yh[(size_t)row * DD + c] = hb;
            yl[(size_t)row * DD + c] = bf16_bits(v - bf16_val(hb));
        } else {
            yh[(size_t)row * DD + c] = fp16_bits(v);
        }
    }
}

// ---------------- launch -----------------------------------------------------
extern "C" void kernel_launch(void* const* d_in, const int* in_sizes, int n_in,
                              void* d_out, int out_size) {
    const float* src_embedded = (const float*)d_in[0];
    const int*   src_mask     = (const int*)d_in[1];
    const void*  tgt_raw      = d_in[2];
    const float* emb   = (const float*)d_in[3];
    const float* pe    = (const float*)d_in[4];
    const float* sa_wq = (const float*)d_in[5];
    const float* sa_wk = (const float*)d_in[6];
    const float* sa_wv = (const float*)d_in[7];
    const float* sa_wo = (const float*)d_in[8];
    const float* sa_bo = (const float*)d_in[9];
    const float* ca_wq = (const float*)d_in[10];
    const float* ca_wk = (const float*)d_in[11];
    const float* ca_wv = (const float*)d_in[12];
    const float* ca_wo = (const float*)d_in[13];
    const float* ca_bo = (const float*)d_in[14];
    const float* ln1_g = (const float*)d_in[15];
    const float* ln1_b = (const float*)d_in[16];
    const float* ln2_g = (const float*)d_in[17];
    const float* ln2_b = (const float*)d_in[18];
    const float* ln3_g = (const float*)d_in[19];
    const float* ln3_b = (const float*)d_in[20];
    const float* fc1_w = (const float*)d_in[21];
    const float* fc1_b = (const float*)d_in[22];
    const float* fc2_w = (const float*)d_in[23];
    const float* fc2_b = (const float*)d_in[24];
    const float* out_w = (const float*)d_in[25];
    const float* out_b = (const float*)d_in[26];

    float *x0, *pr, *x1, *x2, *x3;
    unsigned short *xh, *xl, *eh, *el, *qkvh, *qkvl, *ath, *ahi, *bhi, *blo;
    cudaGetSymbolAddress((void**)&x0,   g_x0);
    cudaGetSymbolAddress((void**)&pr,   g_pr);
    cudaGetSymbolAddress((void**)&x1,   g_x1);
    cudaGetSymbolAddress((void**)&x2,   g_x2);
    cudaGetSymbolAddress((void**)&x3,   g_x3);
    cudaGetSymbolAddress((void**)&xh,   g_xh);
    cudaGetSymbolAddress((void**)&xl,   g_xl);
    cudaGetSymbolAddress((void**)&eh,   g_eh);
    cudaGetSymbolAddress((void**)&el,   g_el);
    cudaGetSymbolAddress((void**)&qkvh, g_qkvh);
    cudaGetSymbolAddress((void**)&qkvl, g_qkvl);
    cudaGetSymbolAddress((void**)&ath,  g_ath);
    cudaGetSymbolAddress((void**)&ahi,  g_ahi);
    cudaGetSymbolAddress((void**)&bhi,  g_bhi);
    cudaGetSymbolAddress((void**)&blo,  g_blo);

    cudaFuncSetAttribute(mma_gemm<0,1,64>, cudaFuncAttributeMaxDynamicSharedMemorySize, SMEM64);

    float* outp   = (float*)d_out;
    float* logits = outp;
    float* tgt_out = nullptr;
    long long need = (long long)NROWS * NVOCAB;
    if ((long long)out_size >= need + NROWS) tgt_out = outp + need;

    dim3 gD64(DD / 64, NROWS / 64);
    dim3 gQKV64((3 * DD) / 64, NROWS / 64);
    dim3 gKV64((2 * DD) / 64, NROWS / 64);
    dim3 gF(NDFF / 64, NROWS / 128);
    dim3 gV(NVPAD / 64, NROWS / 128);
    dim3 gAttn(TT / 64, HH, BB);
    const int WB = 256;

    prep_tgt_kernel<<<(NROWS + 127) / 128, 128>>>(tgt_raw, tgt_out);
    embed_kernel<<<(NROWS * DD) / 256, 256>>>(emb, pe);
    conv_w4<<<(DD*DD)/(4*WB), WB>>>(sa_wq, bhi, blo, DD, DD, 3*DD, 0);
    conv_w4<<<(DD*DD)/(4*WB), WB>>>(sa_wk, bhi, blo, DD, DD, 3*DD, DD);
    conv_w4<<<(DD*DD)/(4*WB), WB>>>(sa_wv, bhi, blo, DD, DD, 3*DD, 2*DD);
    mma_gemm<0,1,64><<<gQKV64, 128, SMEM64>>>(xh, xl, bhi, blo, nullptr, nullptr,
                                              qkvh, qkvl, NROWS, 3*DD, DD, 3*DD, 3*DD);
    attn_mma<0><<<gAttn, 128>>>(qkvh, qkvl, qkvh + DD, qkvl + DD,
                                qkvh + 2*DD, qkvl + 2*DD, ath, nullptr);
    conv_pad_h4<<<(DD*DD)/(4*WB), WB>>>(sa_wo, bhi, DD, DD, DD);
    mma_gemm_h<0,0,64><<<gD64, 128, SMEM_H64>>>(ath, bhi, sa_bo, pr, nullptr,
                                                NROWS, DD, DD, DD, DD);
    ln_kernel<0><<<NROWS / 4, 128>>>(x0, pr, ln1_g, ln1_b, x1, xh, xl);

    // ---- cross-attention block ----
    encmask_kernel<<<(NROWS * DD) / 256, 256>>>(src_embedded, src_mask);
    conv_w4<<<(DD*DD)/(4*WB), WB>>>(ca_wq, bhi, blo, DD, DD, DD, 0);
    mma_gemm<0,1,64><<<gD64, 128, SMEM64>>>(xh, xl, bhi, blo, nullptr, nullptr,
                                            qkvh, qkvl, NROWS, DD, DD, DD, 3*DD);
    conv_w4<<<(DD*DD)/(4*WB), WB>>>(ca_wk, bhi, blo, DD, DD, 2*DD, 0);
    conv_w4<<<(DD*DD)/(4*WB), WB>>>(ca_wv, bhi, blo, DD, DD, 2*DD, DD);
    mma_gemm<0,1,64><<<gKV64, 128, SMEM64>>>(eh, el, bhi, blo, nullptr, nullptr,
                                             qkvh + DD, qkvl + DD, NROWS, 2*DD, DD, 2*DD, 3*DD);
    attn_mma<1><<<gAttn, 128>>>(qkvh, qkvl, qkvh + DD, qkvl + DD,
                                qkvh + 2*DD, qkvl + 2*DD, ath, src_mask);
    conv_pad_h4<<<(DD*DD)/(4*WB), WB>>>(ca_wo, bhi, DD, DD, DD);
    mma_gemm_h<0,0,64><<<gD64, 128, SMEM_H64>>>(ath, bhi, ca_bo, pr, nullptr,
                                                NROWS, DD, DD, DD, DD);
    // LN2 emits fp16 (feeds fc1 only)
    ln_kernel<1><<<NROWS / 4, 128>>>(x1, pr, ln2_g, ln2_b, x2, xh, nullptr);

    // ---- FFN (fp16 single-pass) ----
    conv_pad_h4<<<(DD*NDFF)/(4*WB), WB>>>(fc1_w, bhi, DD, NDFF, NDFF);
    mma_gemm_h<1,1,128><<<gF, 256, SMEM_H128>>>(xh, bhi, fc1_b, nullptr, ahi,
                                                NROWS, NDFF, DD, NDFF, NDFF);
    conv_pad_h4<<<(NDFF*DD)/(4*WB), WB>>>(fc2_w, bhi, NDFF, DD, DD);
    mma_gemm_h<0,0,64><<<gD64, 128, SMEM_H64>>>(ahi, bhi, fc2_b, pr, nullptr,
                                                NROWS, DD, NDFF, DD, DD);
    // LN3 emits fp16 (feeds vocab only)
    ln_kernel<1><<<NROWS / 4, 128>>>(x2, pr, ln3_g, ln3_b, x3, xh, nullptr);

    // ---- vocab projection: fp16 single-pass ----
    conv_pad_h4<<<(DD*NVPAD)/(4*WB), WB>>>(out_w, bhi, DD, NVOCAB, NVPAD);
    mma_gemm_h<0,0,128><<<gV, 256, SMEM_H128>>>(xh, bhi, out_b, logits, nullptr,
                                                NROWS, NVOCAB, DD, NVPAD, NVOCAB);
}

// round 16
// speedup vs baseline: 1.7402x; 1.0981x over previous
#include <cuda_runtime.h>
#include <cuda_bf16.h>
#include <cuda_fp16.h>
#include <cstdint>
#include <cstdio>
#include <math.h>
#include <float.h>

#define BB 2
#define SS 2048
#define TT 2048
#define NVOCAB 25426
#define NVPAD 25472
#define DD 256
#define HH 8
#define DHH 32
#define NDFF 2048
#define NROWS (BB*TT)
#define T0LEN (TT-1)

// ---------------- scratch ----------------------------------------------------
static __device__ float g_x0 [NROWS*DD];
static __device__ float g_pr [NROWS*DD];
static __device__ float g_x1 [NROWS*DD];
static __device__ float g_x2 [NROWS*DD];
static __device__ float g_x3 [NROWS*DD];
static __device__ int   g_tgt[NROWS];
// bf16 hi/lo buffers (xh doubles as fp16 buffer after LN2/LN3)
static __device__ unsigned short g_xh [NROWS*DD],   g_xl [NROWS*DD];
static __device__ unsigned short g_eh [NROWS*DD],   g_el [NROWS*DD];
static __device__ unsigned short g_qkvh[NROWS*3*DD], g_qkvl[NROWS*3*DD];
static __device__ unsigned short g_vh [NROWS*DD];   // fp16 V
static __device__ unsigned short g_ath[NROWS*DD];   // fp16 attention out
static __device__ unsigned short g_ahi[NROWS*NDFF]; // fp16 ff1
static __device__ unsigned short g_bhi[DD*NVPAD],   g_blo[DD*NVPAD];

// ---------------- helpers ----------------------------------------------------
__device__ __forceinline__ unsigned short bf16_bits(float v) {
    return (unsigned short)__bfloat16_as_ushort(__float2bfloat16(v));
}
__device__ __forceinline__ float bf16_val(unsigned short u) {
    return __bfloat162float(__ushort_as_bfloat16(u));
}
__device__ __forceinline__ unsigned short fp16_bits(float v) {
    return (unsigned short)__half_as_ushort(__float2half_rn(v));
}
__device__ __forceinline__ unsigned int pack_bf16x2(float lo, float hi) {
    unsigned int r;
    asm("cvt.rn.bf16x2.f32 %0, %1, %2;" : "=r"(r) : "f"(hi), "f"(lo));
    return r;
}
__device__ __forceinline__ unsigned int pack_f16x2(float lo, float hi) {
    unsigned int r;
    asm("cvt.rn.f16x2.f32 %0, %1, %2;" : "=r"(r) : "f"(hi), "f"(lo));
    return r;
}
__device__ __forceinline__ float fexp2(float t) {
    t = fmaxf(t, -126.0f);
    float z  = t + 12582912.0f;
    float fi = z - 12582912.0f;
    float f  = t - fi;
    int   ii = __float_as_int(z) - 0x4B400000;
    float p = 1.54035304e-4f;
    p = fmaf(p, f, 1.33335581e-3f);
    p = fmaf(p, f, 9.61812910e-3f);
    p = fmaf(p, f, 5.55041087e-2f);
    p = fmaf(p, f, 2.40226507e-1f);
    p = fmaf(p, f, 6.93147181e-1f);
    p = fmaf(p, f, 1.0f);
    return __int_as_float(__float_as_int(p) + (ii << 23));
}
#define L2E 1.4426950408889634f

// ---------------- prep kernels -----------------------------------------------
__global__ void prep_tgt_kernel(const void* __restrict__ tgt_raw,
                                float* __restrict__ tgt_out) {
    __shared__ int s_odd;
    if (threadIdx.x == 0) s_odd = 0;
    __syncthreads();
    const int* raw = (const int*)tgt_raw;
    int local = 0;
    for (int i = threadIdx.x; i < BB * T0LEN; i += blockDim.x)
        if ((i & 1) && raw[i] != 0) local = 1;
    if (local) atomicOr(&s_odd, 1);
    __syncthreads();
    int is64 = s_odd ? 0 : 1;

    int idx = blockIdx.x * blockDim.x + threadIdx.x;
    if (idx >= NROWS) return;
    int b = idx / TT, t = idx % TT;
    int id;
    if (t == 0) id = NVOCAB;
    else {
        size_t src = (size_t)b * T0LEN + (t - 1);
        if (is64) id = (int)((const long long*)tgt_raw)[src];
        else      id = ((const int*)tgt_raw)[src];
    }
    if (id < 0) id = 0;
    if (id > NVOCAB) id = NVOCAB;
    g_tgt[idx] = id;
    if (tgt_out) tgt_out[idx] = (t == 0) ? 0.0f : (float)id;
}

__global__ void embed_kernel(const float* __restrict__ emb,
                             const float* __restrict__ pe) {
    int idx = blockIdx.x * blockDim.x + threadIdx.x;
    if (idx >= NROWS * DD) return;
    int row = idx >> 8, d = idx & 255, t = row & (TT - 1);
    int id = g_tgt[row];
    float v = 2.0f * emb[(size_t)id * DD + d] + pe[(size_t)t * DD + d];
    g_x0[idx] = v;
    unsigned short h = bf16_bits(v);
    g_xh[idx] = h;
    g_xl[idx] = bf16_bits(v - bf16_val(h));
}

__global__ void encmask_kernel(const float* __restrict__ src,
                               const int* __restrict__ mask) {
    int idx = blockIdx.x * blockDim.x + threadIdx.x;
    if (idx >= NROWS * DD) return;
    float v = mask[idx >> 8] ? src[idx] : 0.0f;
    unsigned short h = bf16_bits(v);
    g_eh[idx] = h;
    g_el[idx] = bf16_bits(v - bf16_val(h));
}

__global__ void conv_w4(const float* __restrict__ x,
                        unsigned short* __restrict__ hi,
                        unsigned short* __restrict__ lo,
                        int K, int N, int ldb, int col0) {
    int i = (blockIdx.x * blockDim.x + threadIdx.x) * 4;
    if (i >= K * N) return;
    int r = i / N, c = i % N;
    float4 v = *reinterpret_cast<const float4*>(x + (size_t)r * N + c);
    ushort4 h, l;
    h.x = bf16_bits(v.x); l.x = bf16_bits(v.x - bf16_val(h.x));
    h.y = bf16_bits(v.y); l.y = bf16_bits(v.y - bf16_val(h.y));
    h.z = bf16_bits(v.z); l.z = bf16_bits(v.z - bf16_val(h.z));
    h.w = bf16_bits(v.w); l.w = bf16_bits(v.w - bf16_val(h.w));
    size_t dst = (size_t)r * ldb + col0 + c;
    *reinterpret_cast<ushort4*>(hi + dst) = h;
    *reinterpret_cast<ushort4*>(lo + dst) = l;
}

// fp16 pad convert (single array, zero pad to ldb)
__global__ void conv_pad_h4(const float* __restrict__ x,
                            unsigned short* __restrict__ hi,
                            int K, int N, int ldb) {
    int i = (blockIdx.x * blockDim.x + threadIdx.x) * 4;
    if (i >= K * ldb) return;
    int r = i / ldb, c = i % ldb;
    ushort4 h;
    float vv[4];
    #pragma unroll
    for (int j = 0; j < 4; j++) {
        int cc = c + j;
        vv[j] = (cc < N) ? x[(size_t)r * N + cc] : 0.0f;
    }
    h.x = fp16_bits(vv[0]); h.y = fp16_bits(vv[1]);
    h.z = fp16_bits(vv[2]); h.w = fp16_bits(vv[3]);
    *reinterpret_cast<ushort4*>(hi + i) = h;
}

// ---------------- MMA primitives ---------------------------------------------
#define MMA_BF16(ac, a, b0, b1)                                              \
    asm volatile("mma.sync.aligned.m16n8k16.row.col.f32.bf16.bf16.f32 "      \
                 "{%0,%1,%2,%3},{%4,%5,%6,%7},{%8,%9},{%0,%1,%2,%3};"        \
                 : "+f"(ac[0]), "+f"(ac[1]), "+f"(ac[2]), "+f"(ac[3])        \
                 : "r"(a[0]), "r"(a[1]), "r"(a[2]), "r"(a[3]),               \
                   "r"(b0), "r"(b1))

#define MMA_F16(ac, a, b0, b1)                                               \
    asm volatile("mma.sync.aligned.m16n8k16.row.col.f32.f16.f16.f32 "        \
                 "{%0,%1,%2,%3},{%4,%5,%6,%7},{%8,%9},{%0,%1,%2,%3};"        \
                 : "+f"(ac[0]), "+f"(ac[1]), "+f"(ac[2]), "+f"(ac[3])        \
                 : "r"(a[0]), "r"(a[1]), "r"(a[2]), "r"(a[3]),               \
                   "r"(b0), "r"(b1))

__device__ __forceinline__ void ldsm_x4(unsigned int* r, const unsigned short* p) {
    unsigned int sa = (unsigned int)__cvta_generic_to_shared(p);
    asm volatile("ldmatrix.sync.aligned.m8n8.x4.shared.b16 {%0,%1,%2,%3},[%4];"
                 : "=r"(r[0]), "=r"(r[1]), "=r"(r[2]), "=r"(r[3]) : "r"(sa));
}
__device__ __forceinline__ void ldsm_x4t(unsigned int* r, const unsigned short* p) {
    unsigned int sa = (unsigned int)__cvta_generic_to_shared(p);
    asm volatile("ldmatrix.sync.aligned.m8n8.x4.trans.shared.b16 {%0,%1,%2,%3},[%4];"
                 : "=r"(r[0]), "=r"(r[1]), "=r"(r[2]), "=r"(r[3]) : "r"(sa));
}
__device__ __forceinline__ void cp16(unsigned short* sdst, const unsigned short* gsrc) {
    unsigned int d = (unsigned int)__cvta_generic_to_shared(sdst);
    asm volatile("cp.async.cg.shared.global [%0], [%1], 16;" :: "r"(d), "l"(gsrc));
}
#define CP_COMMIT() asm volatile("cp.async.commit_group;" ::: "memory")
#define CP_WAIT0()  asm volatile("cp.async.wait_group 0;" ::: "memory")
#define CP_WAIT1()  asm volatile("cp.async.wait_group 1;" ::: "memory")

// ---------------- tensor-core GEMM (bf16 split, BM template) -----------------
// OUTM 0: fp32 C. OUTM 1: bf16 hi/lo Ch/Cl. OUTM 2: fp16 single Ch.
#define LDA_S 40
#define LDB_S 72

template<int ACT, int OUTM, int BM>
__global__ __launch_bounds__(BM * 2)
void mma_gemm(const unsigned short* __restrict__ Ahi,
              const unsigned short* __restrict__ Alo,
              const unsigned short* __restrict__ Bhi,
              const unsigned short* __restrict__ Blo,
              const float* __restrict__ bias, float* __restrict__ C,
              unsigned short* __restrict__ Ch, unsigned short* __restrict__ Cl,
              int M, int N, int K, int ldb, int ldc) {
    constexpr int A_SZ = BM * LDA_S;
    constexpr int STG  = 2 * A_SZ + 2 * 32 * LDB_S;
    constexpr int AH = 0, AL = A_SZ, BH = 2 * A_SZ, BL = 2 * A_SZ + 32 * LDB_S;
    extern __shared__ __align__(16) unsigned short smem_u[];

    const int tid = threadIdx.x, lane = tid & 31, warp = tid >> 5;
    const int wm = warp >> 1, wn = warp & 1;
    const int m0 = blockIdx.y * BM, n0 = blockIdx.x * 64;
    const int ar = tid >> 1, ac = (tid & 1) * 16;

    float acc[2][4][4] = {};

    auto issue_tile = [&](int k0, int st) {
        unsigned short* base = smem_u + st * STG;
        const unsigned short* gAh = Ahi + (size_t)(m0 + ar) * K + k0 + ac;
        const unsigned short* gAl = Alo + (size_t)(m0 + ar) * K + k0 + ac;
        cp16(base + AH + ar * LDA_S + ac,     gAh);
        cp16(base + AH + ar * LDA_S + ac + 8, gAh + 8);
        cp16(base + AL + ar * LDA_S + ac,     gAl);
        cp16(base + AL + ar * LDA_S + ac + 8, gAl + 8);
        if (BM == 128) {
            const int br = tid >> 3, bc = (tid & 7) * 8;
            const size_t gb = (size_t)(k0 + br) * ldb + n0 + bc;
            cp16(base + BH + br * LDB_S + bc, Bhi + gb);
            cp16(base + BL + br * LDB_S + bc, Blo + gb);
        } else {
            const int br = tid >> 2, bc = (tid & 3) * 16;
            const size_t gb = (size_t)(k0 + br) * ldb + n0 + bc;
            cp16(base + BH + br * LDB_S + bc,     Bhi + gb);
            cp16(base + BH + br * LDB_S + bc + 8, Bhi + gb + 8);
            cp16(base + BL + br * LDB_S + bc,     Blo + gb);
            cp16(base + BL + br * LDB_S + bc + 8, Blo + gb + 8);
        }
    };

    issue_tile(0, 0);
    CP_COMMIT();

    int buf = 0;
    for (int k0 = 0; k0 < K; k0 += 32) {
        if (k0 + 32 < K) { issue_tile(k0 + 32, buf ^ 1); CP_COMMIT(); CP_WAIT1(); }
        else             { CP_WAIT0(); }
        __syncthreads();

        const unsigned short* sAh = smem_u + buf * STG + AH;
        const unsigned short* sAl = smem_u + buf * STG + AL;
        const unsigned short* sBh = smem_u + buf * STG + BH;
        const unsigned short* sBl = smem_u + buf * STG + BL;

        #pragma unroll
        for (int ks = 0; ks < 32; ks += 16) {
            unsigned int ah[2][4], al[2][4];
            #pragma unroll
            for (int mi = 0; mi < 2; mi++) {
                const int off = (wm * 32 + mi * 16 + (lane & 15)) * LDA_S
                                + ks + (lane >> 4) * 8;
                ldsm_x4(ah[mi], &sAh[off]);
                ldsm_x4(al[mi], &sAl[off]);
            }
            unsigned int bh[2][4], bl[2][4];
            #pragma unroll
            for (int p = 0; p < 2; p++) {
                const int off = (ks + (lane & 15)) * LDB_S
                                + wn * 32 + p * 16 + (lane >> 4) * 8;
                ldsm_x4t(bh[p], &sBh[off]);
                ldsm_x4t(bl[p], &sBl[off]);
            }
            #pragma unroll
            for (int mi = 0; mi < 2; mi++) {
                #pragma unroll
                for (int ni = 0; ni < 4; ni++) {
                    unsigned int bh0 = bh[ni >> 1][(ni & 1) * 2];
                    unsigned int bh1 = bh[ni >> 1][(ni & 1) * 2 + 1];
                    unsigned int bl0 = bl[ni >> 1][(ni & 1) * 2];
                    unsigned int bl1 = bl[ni >> 1][(ni & 1) * 2 + 1];
                    MMA_BF16(acc[mi][ni], ah[mi], bh0, bh1);
                    MMA_BF16(acc[mi][ni], ah[mi], bl0, bl1);
                    MMA_BF16(acc[mi][ni], al[mi], bh0, bh1);
                }
            }
        }
        __syncthreads();
        buf ^= 1;
    }

    const int grp = lane >> 2, t4 = lane & 3;
    #pragma unroll
    for (int mi = 0; mi < 2; mi++) {
        #pragma unroll
        for (int ni = 0; ni < 4; ni++) {
            int row = m0 + wm * 32 + mi * 16 + grp;
            int col = n0 + wn * 32 + ni * 8 + t4 * 2;
            #pragma unroll
            for (int hv = 0; hv < 2; hv++) {
                int r = row + hv * 8;
                #pragma unroll
                for (int cc = 0; cc < 2; cc++) {
                    int n = col + cc;
                    if (n >= N) continue;
                    float v = acc[mi][ni][hv * 2 + cc] + (bias ? bias[n] : 0.0f);
                    if (ACT == 1) v = 0.5f * v * (1.0f + erff(v * 0.70710678118654752f));
                    if (OUTM == 0) {
                        C[(size_t)r * ldc + n] = v;
                    } else if (OUTM == 1) {
                        unsigned short h = bf16_bits(v);
                        Ch[(size_t)r * ldc + n] = h;
                        Cl[(size_t)r * ldc + n] = bf16_bits(v - bf16_val(h));
                    } else {
                        Ch[(size_t)r * ldc + n] = fp16_bits(v);
                    }
                }
            }
        }
    }
}

#define STG64    (2*64*LDA_S + 2*32*LDB_S)
#define SMEM64   (2 * STG64 * 2)

// ---------------- fp16 single-pass GEMM: BM x 64 x BK32 ----------------------
template<int ACT, int OUTH, int BM>
__global__ __launch_bounds__(BM * 2)
void mma_gemm_h(const unsigned short* __restrict__ Ah,
                const unsigned short* __restrict__ Bh,
                const float* __restrict__ bias, float* __restrict__ C,
                unsigned short* __restrict__ Ch,
                int M, int N, int K, int ldb, int ldc) {
    constexpr int A_SZ = BM * LDA_S;
    constexpr int STG  = A_SZ + 32 * LDB_S;
    constexpr int AH = 0, BH = A_SZ;
    extern __shared__ __align__(16) unsigned short smem_u[];

    const int tid = threadIdx.x, lane = tid & 31, warp = tid >> 5;
    const int wm = warp >> 1, wn = warp & 1;
    const int m0 = blockIdx.y * BM, n0 = blockIdx.x * 64;
    const int ar = tid >> 1, ac = (tid & 1) * 16;

    float acc[2][4][4] = {};

    auto issue_tile = [&](int k0, int st) {
        unsigned short* base = smem_u + st * STG;
        const unsigned short* gA = Ah + (size_t)(m0 + ar) * K + k0 + ac;
        cp16(base + AH + ar * LDA_S + ac,     gA);
        cp16(base + AH + ar * LDA_S + ac + 8, gA + 8);
        if (BM == 128) {
            const int br = tid >> 3, bc = (tid & 7) * 8;
            const size_t gb = (size_t)(k0 + br) * ldb + n0 + bc;
            cp16(base + BH + br * LDB_S + bc, Bh + gb);
        } else {
            const int br = tid >> 2, bc = (tid & 3) * 16;
            const size_t gb = (size_t)(k0 + br) * ldb + n0 + bc;
            cp16(base + BH + br * LDB_S + bc,     Bh + gb);
            cp16(base + BH + br * LDB_S + bc + 8, Bh + gb + 8);
        }
    };

    issue_tile(0, 0);
    CP_COMMIT();

    int buf = 0;
    for (int k0 = 0; k0 < K; k0 += 32) {
        if (k0 + 32 < K) { issue_tile(k0 + 32, buf ^ 1); CP_COMMIT(); CP_WAIT1(); }
        else             { CP_WAIT0(); }
        __syncthreads();

        const unsigned short* sA = smem_u + buf * STG + AH;
        const unsigned short* sB = smem_u + buf * STG + BH;

        #pragma unroll
        for (int ks = 0; ks < 32; ks += 16) {
            unsigned int a[2][4];
            #pragma unroll
            for (int mi = 0; mi < 2; mi++) {
                const int off = (wm * 32 + mi * 16 + (lane & 15)) * LDA_S
                                + ks + (lane >> 4) * 8;
                ldsm_x4(a[mi], &sA[off]);
            }
            unsigned int b[2][4];
            #pragma unroll
            for (int p = 0; p < 2; p++) {
                const int off = (ks + (lane & 15)) * LDB_S
                                + wn * 32 + p * 16 + (lane >> 4) * 8;
                ldsm_x4t(b[p], &sB[off]);
            }
            #pragma unroll
            for (int mi = 0; mi < 2; mi++) {
                #pragma unroll
                for (int ni = 0; ni < 4; ni++) {
                    unsigned int b0 = b[ni >> 1][(ni & 1) * 2];
                    unsigned int b1 = b[ni >> 1][(ni & 1) * 2 + 1];
                    MMA_F16(acc[mi][ni], a[mi], b0, b1);
                }
            }
        }
        __syncthreads();
        buf ^= 1;
    }

    const int grp = lane >> 2, t4 = lane & 3;
    #pragma unroll
    for (int mi = 0; mi < 2; mi++) {
        #pragma unroll
        for (int ni = 0; ni < 4; ni++) {
            int row = m0 + wm * 32 + mi * 16 + grp;
            int col = n0 + wn * 32 + ni * 8 + t4 * 2;
            #pragma unroll
            for (int hv = 0; hv < 2; hv++) {
                int r = row + hv * 8;
                #pragma unroll
                for (int cc = 0; cc < 2; cc++) {
                    int n = col + cc;
                    if (n >= N) continue;
                    float v = acc[mi][ni][hv * 2 + cc] + (bias ? bias[n] : 0.0f);
                    if (ACT == 1) v = 0.5f * v * (1.0f + erff(v * 0.70710678118654752f));
                    if (OUTH == 0) C[(size_t)r * ldc + n] = v;
                    else           Ch[(size_t)r * ldc + n] = fp16_bits(v);
                }
            }
        }
    }
}

#define STG_H128  (128*LDA_S + 32*LDB_S)
#define SMEM_H128 (2 * STG_H128 * 2)
#define STG_H64   (64*LDA_S + 32*LDB_S)
#define SMEM_H64  (2 * STG_H64 * 2)

// ---------------- tensor-core flash attention --------------------------------
// QK: bf16 3-split. PV: fp16 single (P fp16, V fp16). Output fp16.
#define LDK 40
#define ATT_SCALE 0.17677669529663687f
#define QKV_LD (3*DD)

template<int MODE>
__global__ __launch_bounds__(128)
void attn_mma(const unsigned short* __restrict__ Qh, const unsigned short* __restrict__ Ql,
              const unsigned short* __restrict__ Kh, const unsigned short* __restrict__ Kl,
              const unsigned short* __restrict__ Vh,
              unsigned short* __restrict__ Oh,
              const int* __restrict__ aux) {
    const int b = blockIdx.z, h = blockIdx.y, blk = blockIdx.x;
    const int tid = threadIdx.x, lane = tid & 31, w = tid >> 5;
    const int grp = lane >> 2, t4 = lane & 3;
    const size_t rowbase = (size_t)b * TT * QKV_LD + h * DHH;
    const size_t vbase   = (size_t)b * TT * DD + h * DHH;

    __shared__ __align__(16) unsigned short sQh[64*LDK], sQl[64*LDK];
    __shared__ __align__(16) unsigned short sKh[64*LDK], sKl[64*LDK];
    __shared__ __align__(16) unsigned short sV [64*LDK];
    __shared__ int sMask[64];

    {
        int r = tid >> 1, cs = (tid & 1) * 16;
        size_t g = rowbase + (size_t)(blk * 64 + r) * QKV_LD + cs;
        *(uint4*)&sQh[r*LDK+cs]   = *(const uint4*)(Qh + g);
        *(uint4*)&sQh[r*LDK+cs+8] = *(const uint4*)(Qh + g + 8);
        *(uint4*)&sQl[r*LDK+cs]   = *(const uint4*)(Ql + g);
        *(uint4*)&sQl[r*LDK+cs+8] = *(const uint4*)(Ql + g + 8);
    }

    const int qi0 = blk * 64 + w * 16 + grp;
    const int qi1 = qi0 + 8;
    bool qv0 = true, qv1 = true;
    int pred = 0;
    if (MODE == 0) {
        qv0 = (g_tgt[b * TT + qi0] != 0);
        qv1 = (g_tgt[b * TT + qi1] != 0);
        pred = (tid < 64) && (g_tgt[b * TT + blk * 64 + tid] == 0);
    }
    int ext = __syncthreads_or(pred);

    unsigned int qfh[2][4], qfl[2][4];
    #pragma unroll
    for (int c = 0; c < 2; c++) {
        const int off = (w * 16 + (lane & 15)) * LDK + c * 16 + (lane >> 4) * 8;
        ldsm_x4(qfh[c], &sQh[off]);
        ldsm_x4(qfl[c], &sQl[off]);
    }

    const int nT = (MODE == 0) ? (ext ? TT / 64 : (blk + 1)) : SS / 64;

    float M0 = -FLT_MAX, M1 = -FLT_MAX, L0 = 0.0f, L1 = 0.0f;
    float O[4][4] = {};

    for (int tile = 0; tile < nT; tile++) {
        const int j0 = tile * 64;
        __syncthreads();
        {
            int r = tid >> 1, cs = (tid & 1) * 16;
            size_t g = rowbase + (size_t)(j0 + r) * QKV_LD + cs;
            *(uint4*)&sKh[r*LDK+cs]   = *(const uint4*)(Kh + g);
            *(uint4*)&sKh[r*LDK+cs+8] = *(const uint4*)(Kh + g + 8);
            *(uint4*)&sKl[r*LDK+cs]   = *(const uint4*)(Kl + g);
            *(uint4*)&sKl[r*LDK+cs+8] = *(const uint4*)(Kl + g + 8);
            size_t gv = vbase + (size_t)(j0 + r) * DD + cs;
            *(uint4*)&sV[r*LDK+cs]    = *(const uint4*)(Vh + gv);
            *(uint4*)&sV[r*LDK+cs+8]  = *(const uint4*)(Vh + gv + 8);
            if (MODE == 1 && tid < 64) sMask[tid] = aux[b * SS + j0 + tid];
        }
        __syncthreads();

        float sc[8][4] = {};
        #pragma unroll
        for (int c = 0; c < 2; c++) {
            #pragma unroll
            for (int g4 = 0; g4 < 4; g4++) {
                unsigned int kbh[4], kbl[4];
                const int off = (g4 * 16 + (lane & 15)) * LDK + c * 16 + (lane >> 4) * 8;
                ldsm_x4(kbh, &sKh[off]);
                ldsm_x4(kbl, &sKl[off]);
                MMA_BF16(sc[2*g4],   qfh[c], kbh[0], kbh[2]);
                MMA_BF16(sc[2*g4],   qfh[c], kbl[0], kbl[2]);
                MMA_BF16(sc[2*g4],   qfl[c], kbh[0], kbh[2]);
                MMA_BF16(sc[2*g4+1], qfh[c], kbh[1], kbh[3]);
                MMA_BF16(sc[2*g4+1], qfh[c], kbl[1], kbl[3]);
                MMA_BF16(sc[2*g4+1], qfl[c], kbh[1], kbh[3]);
            }
        }

        float ml0 = -FLT_MAX, ml1 = -FLT_MAX;
        #pragma unroll
        for (int f = 0; f < 8; f++) {
            const int jc = j0 + f * 8 + t4 * 2;
            bool v00, v01, v10, v11;
            if (MODE == 0) {
                v00 = qv0 && (jc     <= qi0);
                v01 = qv0 && (jc + 1 <= qi0);
                v10 = qv1 && (jc     <= qi1);
                v11 = qv1 && (jc + 1 <= qi1);
            } else {
                bool k0m = sMask[f * 8 + t4 * 2]     != 0;
                bool k1m = sMask[f * 8 + t4 * 2 + 1] != 0;
                v00 = k0m; v01 = k1m; v10 = k0m; v11 = k1m;
            }
            sc[f][0] = v00 ? sc[f][0] * ATT_SCALE : -FLT_MAX;
            sc[f][1] = v01 ? sc[f][1] * ATT_SCALE : -FLT_MAX;
            sc[f][2] = v10 ? sc[f][2] * ATT_SCALE : -FLT_MAX;
            sc[f][3] = v11 ? sc[f][3] * ATT_SCALE : -FLT_MAX;
            ml0 = fmaxf(ml0, fmaxf(sc[f][0], sc[f][1]));
            ml1 = fmaxf(ml1, fmaxf(sc[f][2], sc[f][3]));
        }
        ml0 = fmaxf(ml0, __shfl_xor_sync(0xffffffffu, ml0, 1));
        ml0 = fmaxf(ml0, __shfl_xor_sync(0xffffffffu, ml0, 2));
        ml1 = fmaxf(ml1, __shfl_xor_sync(0xffffffffu, ml1, 1));
        ml1 = fmaxf(ml1, __shfl_xor_sync(0xffffffffu, ml1, 2));

        const float mn0 = fmaxf(M0, ml0), mn1 = fmaxf(M1, ml1);
        const float corr0 = fexp2((M0 - mn0) * L2E);
        const float corr1 = fexp2((M1 - mn1) * L2E);
        L0 *= corr0; L1 *= corr1;
        #pragma unroll
        for (int ni = 0; ni < 4; ni++) {
            O[ni][0] *= corr0; O[ni][1] *= corr0;
            O[ni][2] *= corr1; O[ni][3] *= corr1;
        }

        float ls0 = 0.0f, ls1 = 0.0f;
        unsigned int aP0[8], aP1[8];
        #pragma unroll
        for (int f = 0; f < 8; f++) {
            float p0 = fexp2((sc[f][0] - mn0) * L2E);
            float p1 = fexp2((sc[f][1] - mn0) * L2E);
            float p2 = fexp2((sc[f][2] - mn1) * L2E);
            float p3 = fexp2((sc[f][3] - mn1) * L2E);
            ls0 += p0 + p1; ls1 += p2 + p3;
            aP0[f] = pack_f16x2(p0, p1);
            aP1[f] = pack_f16x2(p2, p3);
        }
        ls0 += __shfl_xor_sync(0xffffffffu, ls0, 1);
        ls0 += __shfl_xor_sync(0xffffffffu, ls0, 2);
        ls1 += __shfl_xor_sync(0xffffffffu, ls1, 1);
        ls1 += __shfl_xor_sync(0xffffffffu, ls1, 2);
        L0 += ls0; L1 += ls1;
        M0 = mn0; M1 = mn1;

        #pragma unroll
        for (int kc = 0; kc < 4; kc++) {
            unsigned int pa[4] = { aP0[2*kc], aP1[2*kc], aP0[2*kc+1], aP1[2*kc+1] };
            #pragma unroll
            for (int ph = 0; ph < 2; ph++) {
                unsigned int vb[4];
                const int off = (kc * 16 + (lane & 15)) * LDK + ph * 16 + (lane >> 4) * 8;
                ldsm_x4t(vb, &sV[off]);
                #pragma unroll
                for (int j = 0; j < 2; j++) {
                    const int ni = ph * 2 + j;
                    MMA_F16(O[ni], pa, vb[2*j], vb[2*j+1]);
                }
            }
        }
    }

    const float inv0 = 1.0f / L0, inv1 = 1.0f / L1;
    const size_t o0 = vbase + (size_t)qi0 * DD;
    const size_t o1 = vbase + (size_t)qi1 * DD;
    #pragma unroll
    for (int ni = 0; ni < 4; ni++) {
        const int n = ni * 8 + t4 * 2;
        Oh[o0 + n]     = fp16_bits(O[ni][0] * inv0);
        Oh[o0 + n + 1] = fp16_bits(O[ni][1] * inv0);
        Oh[o1 + n]     = fp16_bits(O[ni][2] * inv1);
        Oh[o1 + n + 1] = fp16_bits(O[ni][3] * inv1);
    }
}

// ---------------- residual + layernorm ---------------------------------------
// MODE 0: bf16 hi/lo split to yh/yl. MODE 1: fp16 single to yh.
template<int MODE>
__global__ __launch_bounds__(128)
void ln_kernel(const float* __restrict__ x, const float* __restrict__ h,
               const float* __restrict__ g, const float* __restrict__ bvec,
               float* __restrict__ y,
               unsigned short* __restrict__ yh, unsigned short* __restrict__ yl) {
    int row = blockIdx.x * 4 + (threadIdx.x >> 5);
    int lane = threadIdx.x & 31;
    const float* xr = x + (size_t)row * DD;
    const float* hr = h + (size_t)row * DD;
    float vals[8];
    float s = 0.0f;
    #pragma unroll
    for (int u = 0; u < 8; u++) {
        int c = lane + u * 32;
        vals[u] = xr[c] + hr[c];
        s += vals[u];
    }
    #pragma unroll
    for (int off = 16; off > 0; off >>= 1) s += __shfl_xor_sync(0xffffffffu, s, off);
    float mean = s * (1.0f / DD);
    float vs = 0.0f;
    #pragma unroll
    for (int u = 0; u < 8; u++) { float d = vals[u] - mean; vs += d * d; }
    #pragma unroll
    for (int off = 16; off > 0; off >>= 1) vs += __shfl_xor_sync(0xffffffffu, vs, off);
    float inv = rsqrtf(vs * (1.0f / DD) + 1e-5f);
    float* yr = y + (size_t)row * DD;
    #pragma unroll
    for (int u = 0; u < 8; u++) {
        int c = lane + u * 32;
        float v = (vals[u] - mean) * inv * g[c] + bvec[c];
        yr[c] = v;
        if (MODE == 0) {
            unsigned short hb = bf16_bits(v);
            yh[(size_t)row * DD + c] = hb;
            yl[(size_t)row * DD + c] = bf16_bits(v - bf16_val(hb));
        } else {
            yh[(size_t)row * DD + c] = fp16_bits(v);
        }
    }
}

// ---------------- launch -----------------------------------------------------
extern "C" void kernel_launch(void* const* d_in, const int* in_sizes, int n_in,
                              void* d_out, int out_size) {
    const float* src_embedded = (const float*)d_in[0];
    const int*   src_mask     = (const int*)d_in[1];
    const void*  tgt_raw      = d_in[2];
    const float* emb   = (const float*)d_in[3];
    const float* pe    = (const float*)d_in[4];
    const float* sa_wq = (const float*)d_in[5];
    const float* sa_wk = (const float*)d_in[6];
    const float* sa_wv = (const float*)d_in[7];
    const float* sa_wo = (const float*)d_in[8];
    const float* sa_bo = (const float*)d_in[9];
    const float* ca_wq = (const float*)d_in[10];
    const float* ca_wk = (const float*)d_in[11];
    const float* ca_wv = (const float*)d_in[12];
    const float* ca_wo = (const float*)d_in[13];
    const float* ca_bo = (const float*)d_in[14];
    const float* ln1_g = (const float*)d_in[15];
    const float* ln1_b = (const float*)d_in[16];
    const float* ln2_g = (const float*)d_in[17];
    const float* ln2_b = (const float*)d_in[18];
    const float* ln3_g = (const float*)d_in[19];
    const float* ln3_b = (const float*)d_in[20];
    const float* fc1_w = (const float*)d_in[21];
    const float* fc1_b = (const float*)d_in[22];
    const float* fc2_w = (const float*)d_in[23];
    const float* fc2_b = (const float*)d_in[24];
    const float* out_w = (const float*)d_in[25];
    const float* out_b = (const float*)d_in[26];

    float *x0, *pr, *x1, *x2, *x3;
    unsigned short *xh, *xl, *eh, *el, *qkvh, *qkvl, *vh, *ath, *ahi, *bhi, *blo;
    cudaGetSymbolAddress((void**)&x0,   g_x0);
    cudaGetSymbolAddress((void**)&pr,   g_pr);
    cudaGetSymbolAddress((void**)&x1,   g_x1);
    cudaGetSymbolAddress((void**)&x2,   g_x2);
    cudaGetSymbolAddress((void**)&x3,   g_x3);
    cudaGetSymbolAddress((void**)&xh,   g_xh);
    cudaGetSymbolAddress((void**)&xl,   g_xl);
    cudaGetSymbolAddress((void**)&eh,   g_eh);
    cudaGetSymbolAddress((void**)&el,   g_el);
    cudaGetSymbolAddress((void**)&qkvh, g_qkvh);
    cudaGetSymbolAddress((void**)&qkvl, g_qkvl);
    cudaGetSymbolAddress((void**)&vh,   g_vh);
    cudaGetSymbolAddress((void**)&ath,  g_ath);
    cudaGetSymbolAddress((void**)&ahi,  g_ahi);
    cudaGetSymbolAddress((void**)&bhi,  g_bhi);
    cudaGetSymbolAddress((void**)&blo,  g_blo);

    cudaFuncSetAttribute(mma_gemm<0,1,64>, cudaFuncAttributeMaxDynamicSharedMemorySize, SMEM64);
    cudaFuncSetAttribute(mma_gemm<0,2,64>, cudaFuncAttributeMaxDynamicSharedMemorySize, SMEM64);

    float* outp   = (float*)d_out;
    float* logits = outp;
    float* tgt_out = nullptr;
    long long need = (long long)NROWS * NVOCAB;
    if ((long long)out_size >= need + NROWS) tgt_out = outp + need;

    dim3 gD64(DD / 64, NROWS / 64);
    dim3 gQK64((2 * DD) / 64, NROWS / 64);
    dim3 gF(NDFF / 64, NROWS / 128);
    dim3 gV(NVPAD / 64, NROWS / 128);
    dim3 gAttn(TT / 64, HH, BB);
    const int WB = 256;

    prep_tgt_kernel<<<(NROWS + 127) / 128, 128>>>(tgt_raw, tgt_out);
    embed_kernel<<<(NROWS * DD) / 256, 256>>>(emb, pe);
    // ---- self-attention block ----
    conv_w4<<<(DD*DD)/(4*WB), WB>>>(sa_wq, bhi, blo, DD, DD, 2*DD, 0);
    conv_w4<<<(DD*DD)/(4*WB), WB>>>(sa_wk, bhi, blo, DD, DD, 2*DD, DD);
    mma_gemm<0,1,64><<<gQK64, 128, SMEM64>>>(xh, xl, bhi, blo, nullptr, nullptr,
                                             qkvh, qkvl, NROWS, 2*DD, DD, 2*DD, 3*DD);
    conv_w4<<<(DD*DD)/(4*WB), WB>>>(sa_wv, bhi, blo, DD, DD, DD, 0);
    mma_gemm<0,2,64><<<gD64, 128, SMEM64>>>(xh, xl, bhi, blo, nullptr, nullptr,
                                            vh, nullptr, NROWS, DD, DD, DD, DD);
    attn_mma<0><<<gAttn, 128>>>(qkvh, qkvl, qkvh + DD, qkvl + DD, vh, ath, nullptr);
    conv_pad_h4<<<(DD*DD)/(4*WB), WB>>>(sa_wo, bhi, DD, DD, DD);
    mma_gemm_h<0,0,64><<<gD64, 128, SMEM_H64>>>(ath, bhi, sa_bo, pr, nullptr,
                                                NROWS, DD, DD, DD, DD);
    ln_kernel<0><<<NROWS / 4, 128>>>(x0, pr, ln1_g, ln1_b, x1, xh, xl);

    // ---- cross-attention block ----
    encmask_kernel<<<(NROWS * DD) / 256, 256>>>(src_embedded, src_mask);
    conv_w4<<<(DD*DD)/(4*WB), WB>>>(ca_wq, bhi, blo, DD, DD, DD, 0);
    mma_gemm<0,1,64><<<gD64, 128, SMEM64>>>(xh, xl, bhi, blo, nullptr, nullptr,
                                            qkvh, qkvl, NROWS, DD, DD, DD, 3*DD);
    conv_w4<<<(DD*DD)/(4*WB), WB>>>(ca_wk, bhi, blo, DD, DD, DD, 0);
    mma_gemm<0,1,64><<<gD64, 128, SMEM64>>>(eh, el, bhi, blo, nullptr, nullptr,
                                            qkvh + DD, qkvl + DD, NROWS, DD, DD, DD, 3*DD);
    conv_w4<<<(DD*DD)/(4*WB), WB>>>(ca_wv, bhi, blo, DD, DD, DD, 0);
    mma_gemm<0,2,64><<<gD64, 128, SMEM64>>>(eh, el, bhi, blo, nullptr, nullptr,
                                            vh, nullptr, NROWS, DD, DD, DD, DD);
    attn_mma<1><<<gAttn, 128>>>(qkvh, qkvl, qkvh + DD, qkvl + DD, vh, ath, src_mask);
    conv_pad_h4<<<(DD*DD)/(4*WB), WB>>>(ca_wo, bhi, DD, DD, DD);
    mma_gemm_h<0,0,64><<<gD64, 128, SMEM_H64>>>(ath, bhi, ca_bo, pr, nullptr,
                                                NROWS, DD, DD, DD, DD);
    // LN2 emits fp16 (feeds fc1 only)
    ln_kernel<1><<<NROWS / 4, 128>>>(x1, pr, ln2_g, ln2_b, x2, xh, nullptr);

    // ---- FFN (fp16 single-pass) ----
    conv_pad_h4<<<(DD*NDFF)/(4*WB), WB>>>(fc1_w, bhi, DD, NDFF, NDFF);
    mma_gemm_h<1,1,128><<<gF, 256, SMEM_H128>>>(xh, bhi, fc1_b, nullptr, ahi,
                                                NROWS, NDFF, DD, NDFF, NDFF);
    conv_pad_h4<<<(NDFF*DD)/(4*WB), WB>>>(fc2_w, bhi, NDFF, DD, DD);
    mma_gemm_h<0,0,64><<<gD64, 128, SMEM_H64>>>(ahi, bhi, fc2_b, pr, nullptr,
                                                NROWS, DD, NDFF, DD, DD);
    // LN3 emits fp16 (feeds vocab only)
    ln_kernel<1><<<NROWS / 4, 128>>>(x2, pr, ln3_g, ln3_b, x3, xh, nullptr);

    // ---- vocab projection: fp16 single-pass ----
    conv_pad_h4<<<(DD*NVPAD)/(4*WB), WB>>>(out_w, bhi, DD, NVOCAB, NVPAD);
    mma_gemm_h<0,0,128><<<gV, 256, SMEM_H128>>>(xh, bhi, out_b, logits, nullptr,
                                                NROWS, NVOCAB, DD, NVPAD, NVOCAB);
}